// round 10
// baseline (speedup 1.0000x reference)
#include <cuda_runtime.h>
#include <math.h>

#define BATCH 64
#define TSTEPS 1024
#define IND 64
#define HD 512
#define OUTD 64
#define NCTA 128
#define NTHR 512

typedef unsigned long long ull;

// ---------------- persistent device state ----------------
__device__ __align__(16) float g_h1[2][HD * BATCH];        // [j][b], b contiguous
__device__ __align__(16) float g_h2[2][HD * BATCH];
__device__ __align__(16) float g_xT[TSTEPS * IND * BATCH]; // [t][k][b]
__device__ unsigned g_gen;
__device__ unsigned g_count;

// ---------------- grid-wide sense barrier (128 CTAs, 1/SM) ----------------
__device__ __forceinline__ void grid_barrier() {
    __syncthreads();
    if (threadIdx.x == 0) {
        __threadfence();
        volatile unsigned* vg = &g_gen;
        unsigned my = *vg;
        if (atomicAdd(&g_count, 1u) == NCTA - 1u) {
            g_count = 0u;
            __threadfence();
            *vg = my + 1u;
        } else {
            while (*vg == my) { }
        }
        __threadfence();
    }
    __syncthreads();
}

__device__ __forceinline__ float sigf(float x) { return 1.0f / (1.0f + __expf(-x)); }

// ---------------- packed f32x2 helpers ----------------
__device__ __forceinline__ ull splat2(float v) {
    ull r; asm("mov.b64 %0, {%1, %1};" : "=l"(r) : "f"(v)); return r;
}
__device__ __forceinline__ ull pack2(float lo, float hi) {
    ull r; asm("mov.b64 %0, {%1, %2};" : "=l"(r) : "f"(lo), "f"(hi)); return r;
}
__device__ __forceinline__ void ffma2(ull& d, ull a, ull b) {
    asm("fma.rn.f32x2 %0, %1, %2, %0;" : "+l"(d) : "l"(a), "l"(b));
}
__device__ __forceinline__ ull addf2(ull a, ull b) {
    ull r; asm("add.rn.f32x2 %0, %1, %2;" : "=l"(r) : "l"(a), "l"(b)); return r;
}
__device__ __forceinline__ void unpack2(ull v, float& lo, float& hi) {
    asm("mov.b64 {%0, %1}, %2;" : "=f"(lo), "=f"(hi) : "l"(v));
}

// ---------------- SMEM layout (byte offsets) ----------------
#define O_WA   0                 // 576 k * 16 ull (splatted [k][jj][type])
#define O_WB   73728             // 1024 k * 16 ull
#define O_RED  204800            // 8 rows * 128 ulonglong2 = 16384 B
#define O_BA   221184            // 16 ull
#define O_BB   221312
#define O_WO   221440            // 512 f
#define O_BO   223488
#define O_RY   223504            // 8*64 f
#define SMEM_BYTES 225552

// ---------------- MAC pipeline: blocks of 4 k, double buffered ----------------
// One warp covers all 64 b, 4 jj. Lane: bgrp=lane>>2 (8 b), jj=lane&3.
__device__ __forceinline__ void ld4(ulonglong2 (&hb)[8], const float* __restrict__ hsrc,
                                    int k, int boff) {
#pragma unroll
    for (int i = 0; i < 4; ++i) {
        const ulonglong2* p = (const ulonglong2*)(hsrc + (k + i) * 64 + boff);
        hb[2 * i]     = __ldcg(p);
        hb[2 * i + 1] = __ldcg(p + 1);
    }
}
__device__ __forceinline__ void mm4(const ull* __restrict__ wp, const ulonglong2 (&hb)[8],
                                    ull (&acc)[4][4]) {
#pragma unroll
    for (int i = 0; i < 4; ++i) {
        const ulonglong2* w = (const ulonglong2*)(wp + i * 16);
        ulonglong2 wif = w[0], wgo = w[1];
        ulonglong2 hA = hb[2 * i], hB = hb[2 * i + 1];
        ffma2(acc[0][0], wif.x, hA.x); ffma2(acc[0][1], wif.y, hA.x);
        ffma2(acc[0][2], wgo.x, hA.x); ffma2(acc[0][3], wgo.y, hA.x);
        ffma2(acc[1][0], wif.x, hA.y); ffma2(acc[1][1], wif.y, hA.y);
        ffma2(acc[1][2], wgo.x, hA.y); ffma2(acc[1][3], wgo.y, hA.y);
        ffma2(acc[2][0], wif.x, hB.x); ffma2(acc[2][1], wif.y, hB.x);
        ffma2(acc[2][2], wgo.x, hB.x); ffma2(acc[2][3], wgo.y, hB.x);
        ffma2(acc[3][0], wif.x, hB.y); ffma2(acc[3][1], wif.y, hB.y);
        ffma2(acc[3][2], wgo.x, hB.y); ffma2(acc[3][3], wgo.y, hB.y);
    }
}
// n must be a multiple of 4 (36, 28, 8, 64 all are). 8 LDG.128 in flight.
__device__ __forceinline__ void mac_run(const ull* __restrict__ wbase,
                                        const float* __restrict__ hsrc,
                                        int n, int boff, ull (&acc)[4][4]) {
    ulonglong2 hA[8], hB[8];
    ld4(hA, hsrc, 0, boff);
    int k = 0;
    for (; k + 8 <= n; k += 8) {
        ld4(hB, hsrc, k + 4, boff);
        mm4(wbase + k * 16, hA, acc);
        if (k + 8 < n) ld4(hA, hsrc, k + 8, boff);
        mm4(wbase + (k + 4) * 16, hB, acc);
    }
    if (n & 4) mm4(wbase + k * 16, hA, acc);   // tail block already in hA
}

// ---------------- 16-slice tree reduction (16 KB buffer, 7 syncs) ------------
__device__ __forceinline__ void red_store(ulonglong2* sRed, int slot, const ull (&acc)[4][4]) {
#pragma unroll
    for (int i = 0; i < 4; ++i) {
        sRed[(i * 2) * 128 + slot]     = make_ulonglong2(acc[i][0], acc[i][1]);
        sRed[(i * 2 + 1) * 128 + slot] = make_ulonglong2(acc[i][2], acc[i][3]);
    }
}
__device__ __forceinline__ void red_add(const ulonglong2* sRed, int slot, ull (&acc)[4][4]) {
#pragma unroll
    for (int i = 0; i < 4; ++i) {
        ulonglong2 a = sRed[(i * 2) * 128 + slot];
        ulonglong2 b = sRed[(i * 2 + 1) * 128 + slot];
        acc[i][0] = addf2(acc[i][0], a.x); acc[i][1] = addf2(acc[i][1], a.y);
        acc[i][2] = addf2(acc[i][2], b.x); acc[i][3] = addf2(acc[i][3], b.y);
    }
}
__device__ __forceinline__ void reduce16(ull (&acc)[4][4], ulonglong2* sRed,
                                         int warp, int lane) {
    // 16 -> 8 in two passes (buffer holds 4 warps' worth = 128 slots)
    if (warp >= 8 && warp < 12) red_store(sRed, (warp - 8) * 32 + lane, acc);
    __syncthreads();
    if (warp < 4) red_add(sRed, warp * 32 + lane, acc);
    __syncthreads();
    if (warp >= 12) red_store(sRed, (warp - 12) * 32 + lane, acc);
    __syncthreads();
    if (warp >= 4 && warp < 8) red_add(sRed, (warp - 4) * 32 + lane, acc);
    __syncthreads();
    // 8 -> 1 (3 rounds)
    if (warp >= 4 && warp < 8) red_store(sRed, (warp - 4) * 32 + lane, acc);
    __syncthreads();
    if (warp < 4) red_add(sRed, warp * 32 + lane, acc);
    __syncthreads();
    if (warp >= 1 && warp < 4) red_store(sRed, (warp - 1) * 32 + lane, acc);
    __syncthreads();
    if (warp == 0) {
#pragma unroll
        for (int w = 0; w < 3; ++w) red_add(sRed, w * 32 + lane, acc);
    }
}

// ---------------- activations + cell + h store (warp 0 only) ----------------
__device__ __forceinline__ void cell_update(ull (&acc)[4][4], ull (&cc)[4],
                                            float* __restrict__ hdst,
                                            int j0, int jj, int boff) {
    ull hout[4];
#pragma unroll
    for (int bp = 0; bp < 4; ++bp) {
        float gi0, gi1, gf0, gf1, gg0, gg1, go0, go1, c0, c1;
        unpack2(acc[bp][0], gi0, gi1);
        unpack2(acc[bp][1], gf0, gf1);
        unpack2(acc[bp][2], gg0, gg1);
        unpack2(acc[bp][3], go0, go1);
        unpack2(cc[bp], c0, c1);
        c0 = sigf(gf0) * c0 + sigf(gi0) * tanhf(gg0);
        c1 = sigf(gf1) * c1 + sigf(gi1) * tanhf(gg1);
        cc[bp] = pack2(c0, c1);
        hout[bp] = pack2(sigf(go0) * tanhf(c0), sigf(go1) * tanhf(c1));
    }
    ulonglong2* hd = (ulonglong2*)(hdst + (j0 + jj) * 64 + boff);
    hd[0] = make_ulonglong2(hout[0], hout[1]);
    hd[1] = make_ulonglong2(hout[2], hout[3]);
}

// ---------------- y(t) head: CTA c (<64) -> column c; 8-way k split ----------
__device__ __forceinline__ void do_y(int t, const float* __restrict__ h2v,
                                     int c, int tid,
                                     const float* sWO, const float* sBO,
                                     float* sRY, float* __restrict__ out) {
    int b = tid & 63, u = tid >> 6;   // u in 0..7
    if (c < OUTD) {
        float p = 0.0f;
        int k0 = u * 64;
#pragma unroll 8
        for (int k = 0; k < 64; ++k)
            p += __ldcg(h2v + (k0 + k) * 64 + b) * sWO[k0 + k];
        sRY[u * 64 + b] = p;
    }
    __syncthreads();
    if (c < OUTD && u == 0) {
        float y = sBO[0];
#pragma unroll
        for (int m = 0; m < 8; ++m) y += sRY[m * 64 + b];
        out[b * (TSTEPS * OUTD) + t * OUTD + c] = y;
    }
}

extern __shared__ char smem[];

__global__ void __launch_bounds__(NTHR, 1)
lstm_persistent_kernel(const float* __restrict__ x,
                       const float* __restrict__ Wih1, const float* __restrict__ Whh1,
                       const float* __restrict__ bih1, const float* __restrict__ bhh1,
                       const float* __restrict__ Wih2, const float* __restrict__ Whh2,
                       const float* __restrict__ bih2, const float* __restrict__ bhh2,
                       const float* __restrict__ Wout, const float* __restrict__ bout,
                       float* __restrict__ out) {
    ull* sWA = (ull*)(smem + O_WA);
    ull* sWB = (ull*)(smem + O_WB);
    ulonglong2* sRed = (ulonglong2*)(smem + O_RED);
    ull* sBA = (ull*)(smem + O_BA);
    ull* sBB = (ull*)(smem + O_BB);
    float* sWO = (float*)(smem + O_WO);
    float* sBO = (float*)(smem + O_BO);
    float* sRY = (float*)(smem + O_RY);

    const int tid  = threadIdx.x;
    const int c    = blockIdx.x;          // CTA owns j = c*4 .. c*4+3
    const int j0   = c * 4;
    const int warp = tid >> 5;            // = k-slice (0..15)
    const int lane = tid & 31;
    const int jj   = lane & 3;
    const int bgrp = lane >> 2;           // 0..7
    const int boff = bgrp * 8;            // float offset in 64-wide b row (8 b)

    // ---- stage splatted weights into SMEM (once) ----
    for (int i = tid; i < 576 * 16; i += NTHR) {
        int k = i >> 4, r = i & 15, jw = r >> 2, tp = r & 3;
        int row = tp * HD + j0 + jw;
        float v = (k < IND) ? Wih1[row * IND + k] : Whh1[row * HD + (k - IND)];
        sWA[i] = splat2(v);
    }
    for (int i = tid; i < 1024 * 16; i += NTHR) {
        int k = i >> 4, r = i & 15, jw = r >> 2, tp = r & 3;
        int row = tp * HD + j0 + jw;
        float v = (k < HD) ? Wih2[row * HD + k] : Whh2[row * HD + (k - HD)];
        sWB[i] = splat2(v);
    }
    if (tid < 16) {
        int jw = tid >> 2, tp = tid & 3;
        int row = tp * HD + j0 + jw;
        sBA[jw * 4 + tp] = splat2(bih1[row] + bhh1[row]);
        sBB[jw * 4 + tp] = splat2(bih2[row] + bhh2[row]);
    }
    if (c < OUTD) {
        for (int i = tid; i < HD; i += NTHR) sWO[i] = Wout[c * HD + i];
        if (tid == 0) sBO[0] = bout[c];
    }

    // ---- prologue: x -> [t][k][b]; zero h buffers ----
    for (int t = c * (TSTEPS / NCTA); t < (c + 1) * (TSTEPS / NCTA); ++t) {
        for (int i = tid; i < BATCH * IND; i += NTHR) {
            int b = i & 63, k = i >> 6;
            g_xT[t * (IND * BATCH) + k * 64 + b] = x[b * (TSTEPS * IND) + t * IND + k];
        }
    }
    if (c < 64) {
        int gi = c * NTHR + tid;
        g_h1[0][gi] = 0.0f; g_h1[1][gi] = 0.0f;
        g_h2[0][gi] = 0.0f; g_h2[1][gi] = 0.0f;
    }
    grid_barrier();

    ull cc1[4] = {0, 0, 0, 0}, cc2[4] = {0, 0, 0, 0};
    const ull* wA = sWA + jj * 4;
    const ull* wB = sWB + jj * 4;

    for (int t = 0; t < TSTEPS; ++t) {
        const int rp = t & 1, wb2 = rp ^ 1;
        const float* h1r = g_h1[rp];
        const float* h2r = g_h2[rp];
        const float* h1w = g_h1[wb2];

        // ======== phase A: gates1 = x_t W_ih1^T + h1 W_hh1^T + b ========
        ull acc[4][4];
#pragma unroll
        for (int i = 0; i < 4; ++i)
#pragma unroll
            for (int p = 0; p < 4; ++p)
                acc[i][p] = (warp == 0) ? sBA[jj * 4 + p] : 0ull;

        // 16-way k split over concat [x(64) | h1(512)], 36 k per slice
        if (warp == 0) {
            mac_run(wA, g_xT + t * (IND * BATCH), 36, boff, acc);
        } else if (warp == 1) {
            mac_run(wA + 36 * 16, g_xT + t * (IND * BATCH) + 36 * 64, 28, boff, acc);
            mac_run(wA + 64 * 16, h1r, 8, boff, acc);
        } else {
            mac_run(wA + (36 * warp) * 16, h1r + (36 * warp - 64) * 64, 36, boff, acc);
        }
        reduce16(acc, sRed, warp, lane);
        if (warp == 0) cell_update(acc, cc1, g_h1[wb2], j0, jj, boff);

        grid_barrier();   // publish h1(t); the ONLY grid barrier per step

        // deferred y(t-1) from h2(t-1)
        if (t > 0) do_y(t - 1, h2r, c, tid, sWO, sBO, sRY, out);

        // ======== phase B: gates2 = h1(t) W_ih2^T + h2(t-1) W_hh2^T + b ========
#pragma unroll
        for (int i = 0; i < 4; ++i)
#pragma unroll
            for (int p = 0; p < 4; ++p)
                acc[i][p] = (warp == 0) ? sBB[jj * 4 + p] : 0ull;

        // 16-way k split over concat [h1(512) | h2(512)], 64 k per slice
        if (warp < 8) {
            mac_run(wB + (64 * warp) * 16, h1w + (64 * warp) * 64, 64, boff, acc);
        } else {
            mac_run(wB + (64 * warp) * 16, h2r + (64 * warp - 512) * 64, 64, boff, acc);
        }
        reduce16(acc, sRed, warp, lane);
        if (warp == 0) cell_update(acc, cc2, g_h2[wb2], j0, jj, boff);
        __syncthreads();   // protect sRed before next step's phase-A stores
    }

    grid_barrier();
    // final head: h2(T-1) is in buffer ((T-1)&1)^1 == 0
    do_y(TSTEPS - 1, g_h2[0], c, tid, sWO, sBO, sRY, out);
}

extern "C" void kernel_launch(void* const* d_in, const int* in_sizes, int n_in,
                              void* d_out, int out_size) {
    const float* x    = (const float*)d_in[0];
    const float* Wih1 = (const float*)d_in[1];
    const float* Whh1 = (const float*)d_in[2];
    const float* bih1 = (const float*)d_in[3];
    const float* bhh1 = (const float*)d_in[4];
    const float* Wih2 = (const float*)d_in[5];
    const float* Whh2 = (const float*)d_in[6];
    const float* bih2 = (const float*)d_in[7];
    const float* bhh2 = (const float*)d_in[8];
    const float* Wout = (const float*)d_in[9];
    const float* bout = (const float*)d_in[10];
    float* out = (float*)d_out;

    cudaFuncSetAttribute(lstm_persistent_kernel,
                         cudaFuncAttributeMaxDynamicSharedMemorySize, SMEM_BYTES);
    lstm_persistent_kernel<<<NCTA, NTHR, SMEM_BYTES>>>(
        x, Wih1, Whh1, bih1, bhh1, Wih2, Whh2, bih2, bhh2, Wout, bout, out);
}

// round 11
// speedup vs baseline: 1.0705x; 1.0705x over previous
#include <cuda_runtime.h>
#include <math.h>

#define BATCH 64
#define TSTEPS 1024
#define IND 64
#define HD 512
#define OUTD 64
#define NCTA 128
#define NTHR 512

typedef unsigned long long ull;

// ---------------- persistent device state ----------------
__device__ __align__(16) float g_h1[2][HD * BATCH];        // [j][b], b contiguous
__device__ __align__(16) float g_h2[2][HD * BATCH];
__device__ __align__(16) float g_xT[TSTEPS * IND * BATCH]; // [t][k][b]
__device__ unsigned g_gen;
__device__ unsigned g_count;

// ---------------- grid-wide sense barrier (128 CTAs, 1/SM) ----------------
__device__ __forceinline__ void grid_barrier() {
    __syncthreads();
    if (threadIdx.x == 0) {
        __threadfence();
        volatile unsigned* vg = &g_gen;
        unsigned my = *vg;
        if (atomicAdd(&g_count, 1u) == NCTA - 1u) {
            g_count = 0u;
            __threadfence();
            *vg = my + 1u;
        } else {
            while (*vg == my) { }
        }
        __threadfence();
    }
    __syncthreads();
}

__device__ __forceinline__ float sigf(float x) { return 1.0f / (1.0f + __expf(-x)); }

// ---------------- packed f32x2 helpers ----------------
__device__ __forceinline__ ull splat2(float v) {
    ull r; asm("mov.b64 %0, {%1, %1};" : "=l"(r) : "f"(v)); return r;
}
__device__ __forceinline__ ull pack2(float lo, float hi) {
    ull r; asm("mov.b64 %0, {%1, %2};" : "=l"(r) : "f"(lo), "f"(hi)); return r;
}
__device__ __forceinline__ void ffma2(ull& d, ull a, ull b) {
    asm("fma.rn.f32x2 %0, %1, %2, %0;" : "+l"(d) : "l"(a), "l"(b));
}
__device__ __forceinline__ ull addf2(ull a, ull b) {
    ull r; asm("add.rn.f32x2 %0, %1, %2;" : "=l"(r) : "l"(a), "l"(b)); return r;
}
__device__ __forceinline__ void unpack2(ull v, float& lo, float& hi) {
    asm("mov.b64 {%0, %1}, %2;" : "=f"(lo), "=f"(hi) : "l"(v));
}

// ---------------- SMEM layout (byte offsets) ----------------
#define O_WA   0                 // 576 k * 16 ull (splatted [k][jj][type])
#define O_WB   73728             // 1024 k * 16 ull
#define O_RED  204800            // 8 rows * 128 ulonglong2 = 16384 B
#define O_BA   221184            // 16 ull
#define O_BB   221312
#define O_WO   221440            // 512 f
#define O_BO   223488
#define O_RY   223504            // 8*64 f
#define SMEM_BYTES 225552

// ---------------- MAC pipeline: blocks of 4 k, double buffered ----------------
// One warp covers all 64 b, 4 jj. Lane: bgrp=lane>>2 (8 b), jj=lane&3.
__device__ __forceinline__ void ld4(ulonglong2 (&hb)[8], const float* __restrict__ hsrc,
                                    int k, int boff) {
#pragma unroll
    for (int i = 0; i < 4; ++i) {
        const ulonglong2* p = (const ulonglong2*)(hsrc + (k + i) * 64 + boff);
        hb[2 * i]     = __ldcg(p);
        hb[2 * i + 1] = __ldcg(p + 1);
    }
}
__device__ __forceinline__ void mm4(const ull* __restrict__ wp, const ulonglong2 (&hb)[8],
                                    ull (&acc)[4][4]) {
#pragma unroll
    for (int i = 0; i < 4; ++i) {
        const ulonglong2* w = (const ulonglong2*)(wp + i * 16);
        ulonglong2 wif = w[0], wgo = w[1];
        ulonglong2 hA = hb[2 * i], hB = hb[2 * i + 1];
        ffma2(acc[0][0], wif.x, hA.x); ffma2(acc[0][1], wif.y, hA.x);
        ffma2(acc[0][2], wgo.x, hA.x); ffma2(acc[0][3], wgo.y, hA.x);
        ffma2(acc[1][0], wif.x, hA.y); ffma2(acc[1][1], wif.y, hA.y);
        ffma2(acc[1][2], wgo.x, hA.y); ffma2(acc[1][3], wgo.y, hA.y);
        ffma2(acc[2][0], wif.x, hB.x); ffma2(acc[2][1], wif.y, hB.x);
        ffma2(acc[2][2], wgo.x, hB.x); ffma2(acc[2][3], wgo.y, hB.x);
        ffma2(acc[3][0], wif.x, hB.y); ffma2(acc[3][1], wif.y, hB.y);
        ffma2(acc[3][2], wgo.x, hB.y); ffma2(acc[3][3], wgo.y, hB.y);
    }
}
// n must be a multiple of 4 (36, 28, 8, 64 all are). 8 LDG.128 in flight.
__device__ __forceinline__ void mac_run(const ull* __restrict__ wbase,
                                        const float* __restrict__ hsrc,
                                        int n, int boff, ull (&acc)[4][4]) {
    ulonglong2 hA[8], hB[8];
    ld4(hA, hsrc, 0, boff);
    int k = 0;
    for (; k + 8 <= n; k += 8) {
        ld4(hB, hsrc, k + 4, boff);
        mm4(wbase + k * 16, hA, acc);
        if (k + 8 < n) ld4(hA, hsrc, k + 8, boff);
        mm4(wbase + (k + 4) * 16, hB, acc);
    }
    if (n & 4) mm4(wbase + k * 16, hA, acc);   // tail block already in hA
}

// ---------------- 16-slice tree reduction (16 KB buffer, 7 syncs) ------------
__device__ __forceinline__ void red_store(ulonglong2* sRed, int slot, const ull (&acc)[4][4]) {
#pragma unroll
    for (int i = 0; i < 4; ++i) {
        sRed[(i * 2) * 128 + slot]     = make_ulonglong2(acc[i][0], acc[i][1]);
        sRed[(i * 2 + 1) * 128 + slot] = make_ulonglong2(acc[i][2], acc[i][3]);
    }
}
__device__ __forceinline__ void red_add(const ulonglong2* sRed, int slot, ull (&acc)[4][4]) {
#pragma unroll
    for (int i = 0; i < 4; ++i) {
        ulonglong2 a = sRed[(i * 2) * 128 + slot];
        ulonglong2 b = sRed[(i * 2 + 1) * 128 + slot];
        acc[i][0] = addf2(acc[i][0], a.x); acc[i][1] = addf2(acc[i][1], a.y);
        acc[i][2] = addf2(acc[i][2], b.x); acc[i][3] = addf2(acc[i][3], b.y);
    }
}
__device__ __forceinline__ void reduce16(ull (&acc)[4][4], ulonglong2* sRed,
                                         int warp, int lane) {
    // 16 -> 8 in two passes (buffer holds 4 warps' worth = 128 slots)
    if (warp >= 8 && warp < 12) red_store(sRed, (warp - 8) * 32 + lane, acc);
    __syncthreads();
    if (warp < 4) red_add(sRed, warp * 32 + lane, acc);
    __syncthreads();
    if (warp >= 12) red_store(sRed, (warp - 12) * 32 + lane, acc);
    __syncthreads();
    if (warp >= 4 && warp < 8) red_add(sRed, (warp - 4) * 32 + lane, acc);
    __syncthreads();
    // 8 -> 1 (3 rounds)
    if (warp >= 4 && warp < 8) red_store(sRed, (warp - 4) * 32 + lane, acc);
    __syncthreads();
    if (warp < 4) red_add(sRed, warp * 32 + lane, acc);
    __syncthreads();
    if (warp >= 1 && warp < 4) red_store(sRed, (warp - 1) * 32 + lane, acc);
    __syncthreads();
    if (warp == 0) {
#pragma unroll
        for (int w = 0; w < 3; ++w) red_add(sRed, w * 32 + lane, acc);
    }
}

// ---------------- activations + cell + h store (warp 0 only) ----------------
__device__ __forceinline__ void cell_update(ull (&acc)[4][4], ull (&cc)[4],
                                            float* __restrict__ hdst,
                                            int j0, int jj, int boff) {
    ull hout[4];
#pragma unroll
    for (int bp = 0; bp < 4; ++bp) {
        float gi0, gi1, gf0, gf1, gg0, gg1, go0, go1, c0, c1;
        unpack2(acc[bp][0], gi0, gi1);
        unpack2(acc[bp][1], gf0, gf1);
        unpack2(acc[bp][2], gg0, gg1);
        unpack2(acc[bp][3], go0, go1);
        unpack2(cc[bp], c0, c1);
        c0 = sigf(gf0) * c0 + sigf(gi0) * tanhf(gg0);
        c1 = sigf(gf1) * c1 + sigf(gi1) * tanhf(gg1);
        cc[bp] = pack2(c0, c1);
        hout[bp] = pack2(sigf(go0) * tanhf(c0), sigf(go1) * tanhf(c1));
    }
    ulonglong2* hd = (ulonglong2*)(hdst + (j0 + jj) * 64 + boff);
    hd[0] = make_ulonglong2(hout[0], hout[1]);
    hd[1] = make_ulonglong2(hout[2], hout[3]);
}

// ---------------- y(t) head: CTA c (<64) -> column c; 8-way k split ----------
__device__ __forceinline__ void do_y(int t, const float* __restrict__ h2v,
                                     int c, int tid,
                                     const float* sWO, const float* sBO,
                                     float* sRY, float* __restrict__ out) {
    int b = tid & 63, u = tid >> 6;   // u in 0..7
    if (c < OUTD) {
        float p = 0.0f;
        int k0 = u * 64;
#pragma unroll 8
        for (int k = 0; k < 64; ++k)
            p += __ldcg(h2v + (k0 + k) * 64 + b) * sWO[k0 + k];
        sRY[u * 64 + b] = p;
    }
    __syncthreads();
    if (c < OUTD && u == 0) {
        float y = sBO[0];
#pragma unroll
        for (int m = 0; m < 8; ++m) y += sRY[m * 64 + b];
        out[b * (TSTEPS * OUTD) + t * OUTD + c] = y;
    }
}

extern __shared__ char smem[];

__global__ void __launch_bounds__(NTHR, 1)
lstm_persistent_kernel(const float* __restrict__ x,
                       const float* __restrict__ Wih1, const float* __restrict__ Whh1,
                       const float* __restrict__ bih1, const float* __restrict__ bhh1,
                       const float* __restrict__ Wih2, const float* __restrict__ Whh2,
                       const float* __restrict__ bih2, const float* __restrict__ bhh2,
                       const float* __restrict__ Wout, const float* __restrict__ bout,
                       float* __restrict__ out) {
    ull* sWA = (ull*)(smem + O_WA);
    ull* sWB = (ull*)(smem + O_WB);
    ulonglong2* sRed = (ulonglong2*)(smem + O_RED);
    ull* sBA = (ull*)(smem + O_BA);
    ull* sBB = (ull*)(smem + O_BB);
    float* sWO = (float*)(smem + O_WO);
    float* sBO = (float*)(smem + O_BO);
    float* sRY = (float*)(smem + O_RY);

    const int tid  = threadIdx.x;
    const int c    = blockIdx.x;          // CTA owns j = c*4 .. c*4+3
    const int j0   = c * 4;
    const int warp = tid >> 5;            // = k-slice (0..15)
    const int lane = tid & 31;
    const int jj   = lane & 3;
    const int bgrp = lane >> 2;           // 0..7
    const int boff = bgrp * 8;            // float offset in 64-wide b row (8 b)

    // ---- stage splatted weights into SMEM (once) ----
    for (int i = tid; i < 576 * 16; i += NTHR) {
        int k = i >> 4, r = i & 15, jw = r >> 2, tp = r & 3;
        int row = tp * HD + j0 + jw;
        float v = (k < IND) ? Wih1[row * IND + k] : Whh1[row * HD + (k - IND)];
        sWA[i] = splat2(v);
    }
    for (int i = tid; i < 1024 * 16; i += NTHR) {
        int k = i >> 4, r = i & 15, jw = r >> 2, tp = r & 3;
        int row = tp * HD + j0 + jw;
        float v = (k < HD) ? Wih2[row * HD + k] : Whh2[row * HD + (k - HD)];
        sWB[i] = splat2(v);
    }
    if (tid < 16) {
        int jw = tid >> 2, tp = tid & 3;
        int row = tp * HD + j0 + jw;
        sBA[jw * 4 + tp] = splat2(bih1[row] + bhh1[row]);
        sBB[jw * 4 + tp] = splat2(bih2[row] + bhh2[row]);
    }
    if (c < OUTD) {
        for (int i = tid; i < HD; i += NTHR) sWO[i] = Wout[c * HD + i];
        if (tid == 0) sBO[0] = bout[c];
    }

    // ---- prologue: x -> [t][k][b]; zero h buffers ----
    for (int t = c * (TSTEPS / NCTA); t < (c + 1) * (TSTEPS / NCTA); ++t) {
        for (int i = tid; i < BATCH * IND; i += NTHR) {
            int b = i & 63, k = i >> 6;
            g_xT[t * (IND * BATCH) + k * 64 + b] = x[b * (TSTEPS * IND) + t * IND + k];
        }
    }
    if (c < 64) {
        int gi = c * NTHR + tid;
        g_h1[0][gi] = 0.0f; g_h1[1][gi] = 0.0f;
        g_h2[0][gi] = 0.0f; g_h2[1][gi] = 0.0f;
    }
    grid_barrier();

    ull cc1[4] = {0, 0, 0, 0}, cc2[4] = {0, 0, 0, 0};
    const ull* wA = sWA + jj * 4;
    const ull* wB = sWB + jj * 4;

    for (int t = 0; t < TSTEPS; ++t) {
        const int rp = t & 1, wb2 = rp ^ 1;
        const float* h1r = g_h1[rp];
        const float* h2r = g_h2[rp];
        const float* h1w = g_h1[wb2];

        // ======== phase A: gates1 = x_t W_ih1^T + h1 W_hh1^T + b ========
        ull acc[4][4];
#pragma unroll
        for (int i = 0; i < 4; ++i)
#pragma unroll
            for (int p = 0; p < 4; ++p)
                acc[i][p] = (warp == 0) ? sBA[jj * 4 + p] : 0ull;

        // 16-way k split over concat [x(64) | h1(512)], 36 k per slice
        if (warp == 0) {
            mac_run(wA, g_xT + t * (IND * BATCH), 36, boff, acc);
        } else if (warp == 1) {
            mac_run(wA + 36 * 16, g_xT + t * (IND * BATCH) + 36 * 64, 28, boff, acc);
            mac_run(wA + 64 * 16, h1r, 8, boff, acc);
        } else {
            mac_run(wA + (36 * warp) * 16, h1r + (36 * warp - 64) * 64, 36, boff, acc);
        }
        reduce16(acc, sRed, warp, lane);
        if (warp == 0) cell_update(acc, cc1, g_h1[wb2], j0, jj, boff);

        grid_barrier();   // publish h1(t); the ONLY grid barrier per step

        // deferred y(t-1) from h2(t-1)
        if (t > 0) do_y(t - 1, h2r, c, tid, sWO, sBO, sRY, out);

        // ======== phase B: gates2 = h1(t) W_ih2^T + h2(t-1) W_hh2^T + b ========
#pragma unroll
        for (int i = 0; i < 4; ++i)
#pragma unroll
            for (int p = 0; p < 4; ++p)
                acc[i][p] = (warp == 0) ? sBB[jj * 4 + p] : 0ull;

        // 16-way k split over concat [h1(512) | h2(512)], 64 k per slice
        if (warp < 8) {
            mac_run(wB + (64 * warp) * 16, h1w + (64 * warp) * 64, 64, boff, acc);
        } else {
            mac_run(wB + (64 * warp) * 16, h2r + (64 * warp - 512) * 64, 64, boff, acc);
        }
        reduce16(acc, sRed, warp, lane);
        if (warp == 0) cell_update(acc, cc2, g_h2[wb2], j0, jj, boff);
        __syncthreads();   // protect sRed before next step's phase-A stores
    }

    grid_barrier();
    // final head: h2(T-1) is in buffer ((T-1)&1)^1 == 0
    do_y(TSTEPS - 1, g_h2[0], c, tid, sWO, sBO, sRY, out);
}

extern "C" void kernel_launch(void* const* d_in, const int* in_sizes, int n_in,
                              void* d_out, int out_size) {
    const float* x    = (const float*)d_in[0];
    const float* Wih1 = (const float*)d_in[1];
    const float* Whh1 = (const float*)d_in[2];
    const float* bih1 = (const float*)d_in[3];
    const float* bhh1 = (const float*)d_in[4];
    const float* Wih2 = (const float*)d_in[5];
    const float* Whh2 = (const float*)d_in[6];
    const float* bih2 = (const float*)d_in[7];
    const float* bhh2 = (const float*)d_in[8];
    const float* Wout = (const float*)d_in[9];
    const float* bout = (const float*)d_in[10];
    float* out = (float*)d_out;

    cudaFuncSetAttribute(lstm_persistent_kernel,
                         cudaFuncAttributeMaxDynamicSharedMemorySize, SMEM_BYTES);
    lstm_persistent_kernel<<<NCTA, NTHR, SMEM_BYTES>>>(
        x, Wih1, Whh1, bih1, bhh1, Wih2, Whh2, bih2, bhh2, Wout, bout, out);
}

// round 14
// speedup vs baseline: 1.3097x; 1.2234x over previous
#include <cuda_runtime.h>
#include <cuda_bf16.h>
#include <math.h>
#include <stdint.h>

#define BATCH 64
#define TSTEPS 1024
#define IND 64
#define HD 512
#define OUTD 64
#define NCTA 128
#define NTHR 512

typedef __nv_bfloat16 bf16;

// ---- SMEM layout (bytes) ----
#define O_BH1 0          // 16 n x 576 k bf16, row stride 1152, XOR swizzle
#define O_BL1 18432
#define O_BH2 36864      // 16 n x 1024 k, row stride 2048
#define O_BL2 69632
#define O_AB  102400     // 3 bufs x (8KB hi + 8KB lo)
#define O_D   151552     // 2 kh x 64 b x 16 n f32 = 8192
#define O_WO  159744     // 512 f
#define O_RY  161792     // 512 f
#define O_BIA 163840     // 16 f
#define O_BIB 163904     // 16 f
#define O_BO  163968
#define SMEM_BYTES 164000

__device__ __align__(16) bf16 g_xh[TSTEPS * BATCH * IND];
__device__ __align__(16) bf16 g_xl[TSTEPS * BATCH * IND];
__device__ __align__(16) bf16 g_h1h[2][BATCH * HD];   // [b][j]
__device__ __align__(16) bf16 g_h1l[2][BATCH * HD];
__device__ __align__(16) bf16 g_h2h[2][BATCH * HD];
__device__ __align__(16) bf16 g_h2l[2][BATCH * HD];
__device__ __align__(16) float g_h2f[2][HD * BATCH];  // [j][b] for y head
__device__ unsigned g_gen, g_count;

__device__ __forceinline__ void grid_barrier() {
    __syncthreads();
    if (threadIdx.x == 0) {
        __threadfence();
        volatile unsigned* vg = &g_gen;
        unsigned my = *vg;
        if (atomicAdd(&g_count, 1u) == NCTA - 1u) {
            g_count = 0u; __threadfence(); *vg = my + 1u;
        } else { while (*vg == my) { } }
        __threadfence();
    }
    __syncthreads();
}

__device__ __forceinline__ float sigf(float x) { return 1.0f / (1.0f + __expf(-x)); }
__device__ __forceinline__ uint32_t smem_u32(const void* p) {
    uint32_t a;
    asm("{ .reg .u64 t; cvta.to.shared.u64 t, %1; cvt.u32.u64 %0, t; }" : "=r"(a) : "l"(p));
    return a;
}
#define CPA16(dst, src) \
    asm volatile("cp.async.cg.shared.global [%0], [%1], 16;" :: "r"(dst), "l"(src) : "memory")

__device__ __forceinline__ void ldsm4(uint32_t (&r)[4], uint32_t addr) {
    asm volatile("ldmatrix.sync.aligned.m8n8.x4.shared.b16 {%0,%1,%2,%3}, [%4];"
        : "=r"(r[0]), "=r"(r[1]), "=r"(r[2]), "=r"(r[3]) : "r"(addr));
}
__device__ __forceinline__ void ldsm2(uint32_t (&r)[2], uint32_t addr) {
    asm volatile("ldmatrix.sync.aligned.m8n8.x2.shared.b16 {%0,%1}, [%2];"
        : "=r"(r[0]), "=r"(r[1]) : "r"(addr));
}
__device__ __forceinline__ void mma_bf(float (&d)[4], const uint32_t (&a)[4],
                                       const uint32_t (&b)[2]) {
    asm volatile("mma.sync.aligned.m16n8k16.row.col.f32.bf16.bf16.f32 "
        "{%0,%1,%2,%3}, {%4,%5,%6,%7}, {%8,%9}, {%0,%1,%2,%3};"
        : "+f"(d[0]), "+f"(d[1]), "+f"(d[2]), "+f"(d[3])
        : "r"(a[0]), "r"(a[1]), "r"(a[2]), "r"(a[3]), "r"(b[0]), "r"(b[1]));
}

// chunk sources: bf16 [b][k] arrays, row stride st
__device__ __forceinline__ void asrc(int phase, int t, int ch,
                                     const bf16*& ph, const bf16*& pl, int& st) {
    int cur = (t + 1) & 1, prv = t & 1;
    if (!phase) {
        if (ch == 0) { ph = g_xh + t * 4096; pl = g_xl + t * 4096; st = IND; }
        else { int o = (ch - 1) * 64; ph = g_h1h[prv] + o; pl = g_h1l[prv] + o; st = HD; }
    } else {
        if (ch < 8) { int o = ch * 64; ph = g_h1h[cur] + o; pl = g_h1l[cur] + o; st = HD; }
        else { int o = (ch - 8) * 64; ph = g_h2h[prv] + o; pl = g_h2l[prv] + o; st = HD; }
    }
}
// load one 64b x 64k chunk (hi+lo) into buf ch%3 with per-row XOR swizzle
__device__ __forceinline__ void achunk(int phase, int t, int ch, uint32_t su, int tid) {
    const bf16 *ph, *pl; int st;
    asrc(phase, t, ch, ph, pl, st);
    int row = tid >> 3, seg = tid & 7;
    uint32_t d = (uint32_t)(row * 128 + ((seg ^ (row & 7)) << 4));
    uint32_t db = su + O_AB + (uint32_t)(ch % 3) * 16384u + d;
    CPA16(db, ph + row * st + seg * 8);
    CPA16(db + 8192u, pl + row * st + seg * 8);
    asm volatile("cp.async.commit_group;" ::: "memory");
}

// one chunk: warp (mt,nt,kh) does 2 ktiles x 3 split-term mma
__device__ __forceinline__ void do_chunk(uint32_t su, int phase, int ch,
                                         int mt, int nt, int kh, int lane,
                                         float (&acc)[4]) {
    uint32_t ahb = su + O_AB + (uint32_t)(ch % 3) * 16384u;
    uint32_t alb = ahb + 8192u;
    const uint32_t RS = phase ? 2048u : 1152u;
    uint32_t bhb = su + (phase ? O_BH2 : O_BH1);
    uint32_t blb = su + (phase ? O_BL2 : O_BL1);
    int r = mt * 16 + (lane & 15);
    int n = nt * 8 + (lane & 7);
#pragma unroll
    for (int kt = 0; kt < 2; ++kt) {
        int ktl = kh * 2 + kt;
        uint32_t kb = (uint32_t)(ktl * 32 + ((lane >> 4) << 4));
        uint32_t aoff = (uint32_t)(r * 128) + (kb ^ (uint32_t)((r & 7) << 4));
        int kg = ch * 4 + ktl;
        uint32_t kb2 = (uint32_t)(kg * 32 + ((lane & 8) << 1));
        uint32_t boff = (uint32_t)n * RS + (kb2 & ~127u) +
                        ((kb2 & 127u) ^ (uint32_t)((n & 7) << 4));
        uint32_t ah[4], al[4], bh[2], bl[2];
        ldsm4(ah, ahb + aoff);
        ldsm4(al, alb + aoff);
        ldsm2(bh, bhb + boff);
        ldsm2(bl, blb + boff);
        mma_bf(acc, ah, bh);
        mma_bf(acc, al, bh);
        mma_bf(acc, ah, bl);
    }
}

__device__ void run_phase(uint32_t su, int phase, int t, int tid,
                          int mt, int nt, int kh, int lane, float (&acc)[4]) {
    const int nc = phase ? 16 : 9;
    achunk(phase, t, 0, su, tid);
    achunk(phase, t, 1, su, tid);
    for (int ch = 0; ch < nc; ++ch) {
        if (ch + 1 < nc) asm volatile("cp.async.wait_group 1;" ::: "memory");
        else             asm volatile("cp.async.wait_group 0;" ::: "memory");
        __syncthreads();
        do_chunk(su, phase, ch, mt, nt, kh, lane, acc);
        if (ch + 2 < nc) achunk(phase, t, ch + 2, su, tid);
    }
}

__device__ __forceinline__ void do_y(int t, const float* __restrict__ h2v,
                                     int cta, int tid, const float* sWO,
                                     const float* sBO, float* sRY, float* __restrict__ out) {
    int b = tid & 63, u = tid >> 6;
    if (cta < OUTD) {
        float p = 0.0f; int k0 = u * 64;
#pragma unroll 8
        for (int k = 0; k < 64; ++k)
            p += __ldcg(h2v + (k0 + k) * 64 + b) * sWO[k0 + k];
        sRY[u * 64 + b] = p;
    }
    __syncthreads();
    if (cta < OUTD && u == 0) {
        float y = sBO[0];
#pragma unroll
        for (int m = 0; m < 8; ++m) y += sRY[m * 64 + b];
        out[b * (TSTEPS * OUTD) + t * OUTD + cta] = y;
    }
}

extern __shared__ char smem[];

__global__ void __launch_bounds__(NTHR, 1)
lstm_mma_kernel(const float* __restrict__ x,
                const float* __restrict__ Wih1, const float* __restrict__ Whh1,
                const float* __restrict__ bih1, const float* __restrict__ bhh1,
                const float* __restrict__ Wih2, const float* __restrict__ Whh2,
                const float* __restrict__ bih2, const float* __restrict__ bhh2,
                const float* __restrict__ Wout, const float* __restrict__ bout,
                float* __restrict__ out) {
    const int tid = threadIdx.x, c = blockIdx.x, j0 = c * 4;
    const int warp = tid >> 5, lane = tid & 31;
    const int kh = warp >> 3, mt = (warp >> 1) & 3, nt = warp & 1;
    uint32_t su = smem_u32(smem);
    float* sWO = (float*)(smem + O_WO);
    float* sBO = (float*)(smem + O_BO);
    float* sRY = (float*)(smem + O_RY);
    float* sBIA = (float*)(smem + O_BIA);
    float* sBIB = (float*)(smem + O_BIB);
    float* sDf = (float*)(smem + O_D);

    // ---- stage split weights, B row n = jj*4+tp -> weight row tp*HD+j0+jj ----
    for (int i = tid; i < 16 * 576; i += NTHR) {
        int n = i / 576, k = i - n * 576;
        int row = (n & 3) * HD + j0 + (n >> 2);
        float v = (k < IND) ? Wih1[row * IND + k] : Whh1[row * HD + (k - IND)];
        bf16 h = __float2bfloat16(v);
        bf16 l = __float2bfloat16(v - __bfloat162float(h));
        uint32_t k2 = (uint32_t)(k * 2);
        uint32_t off = (uint32_t)n * 1152u + (k2 & ~127u) + ((k2 & 127u) ^ (uint32_t)((n & 7) << 4));
        *(bf16*)(smem + O_BH1 + off) = h;
        *(bf16*)(smem + O_BL1 + off) = l;
    }
    for (int i = tid; i < 16 * 1024; i += NTHR) {
        int n = i >> 10, k = i & 1023;
        int row = (n & 3) * HD + j0 + (n >> 2);
        float v = (k < HD) ? Wih2[row * HD + k] : Whh2[row * HD + (k - HD)];
        bf16 h = __float2bfloat16(v);
        bf16 l = __float2bfloat16(v - __bfloat162float(h));
        uint32_t k2 = (uint32_t)(k * 2);
        uint32_t off = (uint32_t)n * 2048u + (k2 & ~127u) + ((k2 & 127u) ^ (uint32_t)((n & 7) << 4));
        *(bf16*)(smem + O_BH2 + off) = h;
        *(bf16*)(smem + O_BL2 + off) = l;
    }
    if (tid < 16) {
        int row = (tid & 3) * HD + j0 + (tid >> 2);
        sBIA[tid] = bih1[row] + bhh1[row];
        sBIB[tid] = bih2[row] + bhh2[row];
    }
    if (c < OUTD) {
        for (int i = tid; i < HD; i += NTHR) sWO[i] = Wout[c * HD + i];
        if (tid == 0) sBO[0] = bout[c];
    }

    // ---- x -> bf16 split [t][b][k]; zero h state ----
    for (int t = c * (TSTEPS / NCTA); t < (c + 1) * (TSTEPS / NCTA); ++t)
        for (int i = tid; i < BATCH * IND; i += NTHR) {
            int b = i >> 6, k = i & 63;
            float v = x[b * (TSTEPS * IND) + t * IND + k];
            bf16 h = __float2bfloat16(v);
            g_xh[t * 4096 + i] = h;
            g_xl[t * 4096 + i] = __float2bfloat16(v - __bfloat162float(h));
        }
    if (c < 64) {
        int gi = c * NTHR + tid;   // 32768 = BATCH*HD
        bf16 z = __float2bfloat16(0.f);
        g_h1h[0][gi] = z; g_h1h[1][gi] = z;
        g_h1l[0][gi] = z; g_h1l[1][gi] = z;
        g_h2h[0][gi] = z; g_h2h[1][gi] = z;
        g_h2l[0][gi] = z; g_h2l[1][gi] = z;
        g_h2f[0][gi] = 0.f; g_h2f[1][gi] = 0.f;
    }
    grid_barrier();

    float c1 = 0.f, c2 = 0.f;
    const int eb = tid >> 2, ejj = tid & 3;   // epilogue cell: (b, jj), tid<256

    for (int t = 0; t < TSTEPS; ++t) {
        int cur = (t + 1) & 1, prv = t & 1;

        // ======== phase A ========
        float acc[4] = {0.f, 0.f, 0.f, 0.f};
        run_phase(su, 0, t, tid, mt, nt, kh, lane, acc);
        {   // store D fragments
            int r0 = mt * 16 + (lane >> 2), ncol = nt * 8 + (lane & 3) * 2;
            int base = (kh * 64 + r0) * 16 + ncol;
            *(float2*)(sDf + base) = make_float2(acc[0], acc[1]);
            *(float2*)(sDf + base + 128) = make_float2(acc[2], acc[3]);
        }
        __syncthreads();
        if (tid < 256) {
            float4 gx = *(float4*)(sDf + eb * 16 + ejj * 4);
            float4 gy = *(float4*)(sDf + (64 + eb) * 16 + ejj * 4);
            float4 bi = *(float4*)(sBIA + ejj * 4);
            float cc = sigf(gx.y + gy.y + bi.y) * c1 +
                       sigf(gx.x + gy.x + bi.x) * tanhf(gx.z + gy.z + bi.z);
            c1 = cc;
            float h = sigf(gx.w + gy.w + bi.w) * tanhf(cc);
            bf16 hb = __float2bfloat16(h);
            g_h1h[cur][eb * HD + j0 + ejj] = hb;
            g_h1l[cur][eb * HD + j0 + ejj] = __float2bfloat16(h - __bfloat162float(hb));
        }
        grid_barrier();                         // publish h1(t)

        if (t > 0) do_y(t - 1, g_h2f[prv], c, tid, sWO, sBO, sRY, out);

        // ======== phase B ========
        acc[0] = acc[1] = acc[2] = acc[3] = 0.f;
        run_phase(su, 1, t, tid, mt, nt, kh, lane, acc);
        {
            int r0 = mt * 16 + (lane >> 2), ncol = nt * 8 + (lane & 3) * 2;
            int base = (kh * 64 + r0) * 16 + ncol;
            *(float2*)(sDf + base) = make_float2(acc[0], acc[1]);
            *(float2*)(sDf + base + 128) = make_float2(acc[2], acc[3]);
        }
        __syncthreads();
        if (tid < 256) {
            float4 gx = *(float4*)(sDf + eb * 16 + ejj * 4);
            float4 gy = *(float4*)(sDf + (64 + eb) * 16 + ejj * 4);
            float4 bi = *(float4*)(sBIB + ejj * 4);
            float cc = sigf(gx.y + gy.y + bi.y) * c2 +
                       sigf(gx.x + gy.x + bi.x) * tanhf(gx.z + gy.z + bi.z);
            c2 = cc;
            float h = sigf(gx.w + gy.w + bi.w) * tanhf(cc);
            bf16 hb = __float2bfloat16(h);
            g_h2h[cur][eb * HD + j0 + ejj] = hb;
            g_h2l[cur][eb * HD + j0 + ejj] = __float2bfloat16(h - __bfloat162float(hb));
            g_h2f[cur][(j0 + ejj) * 64 + eb] = h;
        }
        __syncthreads();
    }

    grid_barrier();
    do_y(TSTEPS - 1, g_h2f[0], c, tid, sWO, sBO, sRY, out);
}

extern "C" void kernel_launch(void* const* d_in, const int* in_sizes, int n_in,
                              void* d_out, int out_size) {
    const float* x    = (const float*)d_in[0];
    const float* Wih1 = (const float*)d_in[1];
    const float* Whh1 = (const float*)d_in[2];
    const float* bih1 = (const float*)d_in[3];
    const float* bhh1 = (const float*)d_in[4];
    const float* Wih2 = (const float*)d_in[5];
    const float* Whh2 = (const float*)d_in[6];
    const float* bih2 = (const float*)d_in[7];
    const float* bhh2 = (const float*)d_in[8];
    const float* Wout = (const float*)d_in[9];
    const float* bout = (const float*)d_in[10];
    float* out = (float*)d_out;

    cudaFuncSetAttribute(lstm_mma_kernel,
                         cudaFuncAttributeMaxDynamicSharedMemorySize, SMEM_BYTES);
    lstm_mma_kernel<<<NCTA, NTHR, SMEM_BYTES>>>(
        x, Wih1, Whh1, bih1, bhh1, Wih2, Whh2, bih2, bhh2, Wout, bout, out);
}

// round 15
// speedup vs baseline: 2.3587x; 1.8010x over previous
#include <cuda_runtime.h>
#include <cuda_bf16.h>
#include <math.h>
#include <stdint.h>

#define BATCH 64
#define TSTEPS 1024
#define IND 64
#define HD 512
#define OUTD 64
#define NCTA 128
#define NTHR 512

typedef __nv_bfloat16 bf16;

// ---- SMEM layout (bytes) ----
#define O_BH1 0          // 16 n x 576 k bf16, row stride 1152, XOR swizzle
#define O_BL1 18432
#define O_BH2 36864      // 16 n x 1024 k, row stride 2048
#define O_BL2 69632
#define O_AB  102400     // 4 groups x 4 slots x 4KB (2KB hi + 2KB lo)
#define O_D   167936     // 4 kh x 64 b x 16 n f32 = 16384
#define O_WO  184320     // 512 f
#define O_RY  186368     // 512 f
#define O_BIA 188416     // 16 f
#define O_BIB 188480     // 16 f
#define O_BO  188544
#define SMEM_BYTES 188552

__device__ __align__(16) bf16 g_xh[TSTEPS * BATCH * IND];
__device__ __align__(16) bf16 g_xl[TSTEPS * BATCH * IND];
__device__ __align__(16) bf16 g_h1h[2][BATCH * HD];   // [b][j]
__device__ __align__(16) bf16 g_h1l[2][BATCH * HD];
__device__ __align__(16) bf16 g_h2h[2][BATCH * HD];
__device__ __align__(16) bf16 g_h2l[2][BATCH * HD];
__device__ __align__(16) float g_h2f[2][HD * BATCH];  // [j][b] for y head
__device__ unsigned g_gen, g_count;

__device__ __forceinline__ void grid_barrier() {
    __syncthreads();
    if (threadIdx.x == 0) {
        __threadfence();
        volatile unsigned* vg = &g_gen;
        unsigned my = *vg;
        if (atomicAdd(&g_count, 1u) == NCTA - 1u) {
            g_count = 0u; __threadfence(); *vg = my + 1u;
        } else { while (*vg == my) { } }
        __threadfence();
    }
    __syncthreads();
}

__device__ __forceinline__ float sigf(float x) { return 1.0f / (1.0f + __expf(-x)); }
__device__ __forceinline__ uint32_t smem_u32(const void* p) {
    uint32_t a;
    asm("{ .reg .u64 t; cvta.to.shared.u64 t, %1; cvt.u32.u64 %0, t; }" : "=r"(a) : "l"(p));
    return a;
}
#define CPA16(dst, src) \
    asm volatile("cp.async.cg.shared.global [%0], [%1], 16;" :: "r"(dst), "l"(src) : "memory")

__device__ __forceinline__ void ldsm4(uint32_t (&r)[4], uint32_t addr) {
    asm volatile("ldmatrix.sync.aligned.m8n8.x4.shared.b16 {%0,%1,%2,%3}, [%4];"
        : "=r"(r[0]), "=r"(r[1]), "=r"(r[2]), "=r"(r[3]) : "r"(addr));
}
__device__ __forceinline__ void mma_bf(float (&d)[4], const uint32_t (&a)[4],
                                       uint32_t b0, uint32_t b1) {
    asm volatile("mma.sync.aligned.m16n8k16.row.col.f32.bf16.bf16.f32 "
        "{%0,%1,%2,%3}, {%4,%5,%6,%7}, {%8,%9}, {%0,%1,%2,%3};"
        : "+f"(d[0]), "+f"(d[1]), "+f"(d[2]), "+f"(d[3])
        : "r"(a[0]), "r"(a[1]), "r"(a[2]), "r"(a[3]), "r"(b0), "r"(b1));
}

// chunk sources: bf16 [b][k] arrays, row stride st
__device__ __forceinline__ void asrc(int phase, int t, int ch,
                                     const bf16*& ph, const bf16*& pl, int& st) {
    int cur = (t + 1) & 1, prv = t & 1;
    if (!phase) {
        if (ch == 0) { ph = g_xh + t * 4096; pl = g_xl + t * 4096; st = IND; }
        else { int o = (ch - 1) * 64; ph = g_h1h[prv] + o; pl = g_h1l[prv] + o; st = HD; }
    } else {
        if (ch < 8) { int o = ch * 64; ph = g_h1h[cur] + o; pl = g_h1l[cur] + o; st = HD; }
        else { int o = (ch - 8) * 64; ph = g_h2h[prv] + o; pl = g_h2l[prv] + o; st = HD; }
    }
}
// group g loads ITS 16 rows of chunk ch (2KB hi + 2KB lo), XOR swizzle, commit
__device__ __forceinline__ void achunk(int phase, int t, int ch, uint32_t gbase,
                                       int g, int tg) {
    const bf16 *ph, *pl; int st;
    asrc(phase, t, ch, ph, pl, st);
    int lrow = tg >> 3, seg = tg & 7;
    uint32_t d = (uint32_t)(lrow * 128 + ((seg ^ (lrow & 7)) << 4));
    uint32_t db = gbase + (uint32_t)(ch & 3) * 4096u + d;
    const bf16* s = ph + (g * 16 + lrow) * st + seg * 8;
    const bf16* sl = pl + (g * 16 + lrow) * st + seg * 8;
    CPA16(db, s);
    CPA16(db + 2048u, sl);
    asm volatile("cp.async.commit_group;" ::: "memory");
}

// phase pipeline: per-group, 4-slot buffers, named-barrier sync only
__device__ void run_phase(uint32_t su, uint32_t gbase, int phase, int t,
                          int g, int kh, int tg, int lane, float (&acc)[2][4]) {
    const int nc = phase ? 16 : 9;
    const uint32_t RS = phase ? 2048u : 1152u;
    uint32_t bhb = su + (phase ? O_BH2 : O_BH1);
    uint32_t blb = su + (phase ? O_BL2 : O_BL1);
    achunk(phase, t, 0, gbase, g, tg);
    achunk(phase, t, 1, gbase, g, tg);
    achunk(phase, t, 2, gbase, g, tg);
    int lrow = lane & 15;
    uint32_t ksg = (uint32_t)(kh * 2 + (lane >> 4));
    uint32_t aoff = (uint32_t)(lrow * 128) + ((ksg ^ (uint32_t)(lrow & 7)) << 4);
    int n = ((lane >> 4) << 3) + (lane & 7);
    int ks2 = (lane >> 3) & 1;
    for (int ch = 0; ch < nc; ++ch) {
        int rem = nc - 1 - ch;
        if (rem >= 2)      asm volatile("cp.async.wait_group 2;" ::: "memory");
        else if (rem == 1) asm volatile("cp.async.wait_group 1;" ::: "memory");
        else               asm volatile("cp.async.wait_group 0;" ::: "memory");
        asm volatile("bar.sync %0, 128;" :: "r"(1 + g) : "memory");
        uint32_t abase = gbase + (uint32_t)(ch & 3) * 4096u;
        uint32_t ah[4], al[4], bh[4], bl[4];
        ldsm4(ah, abase + aoff);
        ldsm4(al, abase + 2048u + aoff);
        int kg = ch * 4 + kh;
        uint32_t kb2 = (uint32_t)(kg * 32 + (ks2 << 4));
        uint32_t boff = (uint32_t)n * RS + (kb2 & ~127u) +
                        ((kb2 & 127u) ^ (uint32_t)((n & 7) << 4));
        ldsm4(bh, bhb + boff);
        ldsm4(bl, blb + boff);
        mma_bf(acc[0], ah, bh[0], bh[1]);
        mma_bf(acc[1], ah, bh[2], bh[3]);
        mma_bf(acc[0], al, bh[0], bh[1]);
        mma_bf(acc[1], al, bh[2], bh[3]);
        mma_bf(acc[0], ah, bl[0], bl[1]);
        mma_bf(acc[1], ah, bl[2], bl[3]);
        if (ch + 3 < nc) achunk(phase, t, ch + 3, gbase, g, tg);
    }
}

__device__ __forceinline__ void store_d(float* sDf, const float (&acc)[2][4],
                                        int g, int kh, int lane) {
    int base = ((kh * 64) + g * 16 + (lane >> 2)) * 16 + (lane & 3) * 2;
    *(float2*)(sDf + base)           = make_float2(acc[0][0], acc[0][1]);
    *(float2*)(sDf + base + 128)     = make_float2(acc[0][2], acc[0][3]);
    *(float2*)(sDf + base + 8)       = make_float2(acc[1][0], acc[1][1]);
    *(float2*)(sDf + base + 128 + 8) = make_float2(acc[1][2], acc[1][3]);
}

__device__ __forceinline__ void do_y(int t, const float* __restrict__ h2v,
                                     int cta, int tid, const float* sWO,
                                     const float* sBO, float* sRY, float* __restrict__ out) {
    int b = tid & 63, u = tid >> 6;
    if (cta < OUTD) {
        float p = 0.0f; int k0 = u * 64;
#pragma unroll 8
        for (int k = 0; k < 64; ++k)
            p += __ldcg(h2v + (k0 + k) * 64 + b) * sWO[k0 + k];
        sRY[u * 64 + b] = p;
    }
    __syncthreads();
    if (cta < OUTD && u == 0) {
        float y = sBO[0];
#pragma unroll
        for (int m = 0; m < 8; ++m) y += sRY[m * 64 + b];
        out[b * (TSTEPS * OUTD) + t * OUTD + cta] = y;
    }
}

extern __shared__ char smem[];

__global__ void __launch_bounds__(NTHR, 1)
lstm_mma_kernel(const float* __restrict__ x,
                const float* __restrict__ Wih1, const float* __restrict__ Whh1,
                const float* __restrict__ bih1, const float* __restrict__ bhh1,
                const float* __restrict__ Wih2, const float* __restrict__ Whh2,
                const float* __restrict__ bih2, const float* __restrict__ bhh2,
                const float* __restrict__ Wout, const float* __restrict__ bout,
                float* __restrict__ out) {
    const int tid = threadIdx.x, c = blockIdx.x, j0 = c * 4;
    const int lane = tid & 31;
    const int g = tid >> 7;            // mt group 0..3 (warps contiguous)
    const int kh = (tid >> 5) & 3;     // k slice 0..3
    const int tg = tid & 127;          // thread-in-group
    uint32_t su = smem_u32(smem);
    uint32_t gbase = su + O_AB + (uint32_t)g * 16384u;
    float* sWO = (float*)(smem + O_WO);
    float* sBO = (float*)(smem + O_BO);
    float* sRY = (float*)(smem + O_RY);
    float* sBIA = (float*)(smem + O_BIA);
    float* sBIB = (float*)(smem + O_BIB);
    float* sDf = (float*)(smem + O_D);

    // ---- stage split weights: B row n = jj*4+tp -> weight row tp*HD+j0+jj ----
    for (int i = tid; i < 16 * 576; i += NTHR) {
        int n = i / 576, k = i - n * 576;
        int row = (n & 3) * HD + j0 + (n >> 2);
        float v = (k < IND) ? Wih1[row * IND + k] : Whh1[row * HD + (k - IND)];
        bf16 h = __float2bfloat16(v);
        bf16 l = __float2bfloat16(v - __bfloat162float(h));
        uint32_t k2 = (uint32_t)(k * 2);
        uint32_t off = (uint32_t)n * 1152u + (k2 & ~127u) + ((k2 & 127u) ^ (uint32_t)((n & 7) << 4));
        *(bf16*)(smem + O_BH1 + off) = h;
        *(bf16*)(smem + O_BL1 + off) = l;
    }
    for (int i = tid; i < 16 * 1024; i += NTHR) {
        int n = i >> 10, k = i & 1023;
        int row = (n & 3) * HD + j0 + (n >> 2);
        float v = (k < HD) ? Wih2[row * HD + k] : Whh2[row * HD + (k - HD)];
        bf16 h = __float2bfloat16(v);
        bf16 l = __float2bfloat16(v - __bfloat162float(h));
        uint32_t k2 = (uint32_t)(k * 2);
        uint32_t off = (uint32_t)n * 2048u + (k2 & ~127u) + ((k2 & 127u) ^ (uint32_t)((n & 7) << 4));
        *(bf16*)(smem + O_BH2 + off) = h;
        *(bf16*)(smem + O_BL2 + off) = l;
    }
    if (tid < 16) {
        int row = (tid & 3) * HD + j0 + (tid >> 2);
        sBIA[tid] = bih1[row] + bhh1[row];
        sBIB[tid] = bih2[row] + bhh2[row];
    }
    if (c < OUTD) {
        for (int i = tid; i < HD; i += NTHR) sWO[i] = Wout[c * HD + i];
        if (tid == 0) sBO[0] = bout[c];
    }

    // ---- x -> bf16 split [t][b][k]; zero h state ----
    for (int t = c * (TSTEPS / NCTA); t < (c + 1) * (TSTEPS / NCTA); ++t)
        for (int i = tid; i < BATCH * IND; i += NTHR) {
            int b = i >> 6, k = i & 63;
            float v = x[b * (TSTEPS * IND) + t * IND + k];
            bf16 h = __float2bfloat16(v);
            g_xh[t * 4096 + i] = h;
            g_xl[t * 4096 + i] = __float2bfloat16(v - __bfloat162float(h));
        }
    if (c < 64) {
        int gi = c * NTHR + tid;   // 32768 = BATCH*HD
        bf16 z = __float2bfloat16(0.f);
        g_h1h[0][gi] = z; g_h1h[1][gi] = z;
        g_h1l[0][gi] = z; g_h1l[1][gi] = z;
        g_h2h[0][gi] = z; g_h2h[1][gi] = z;
        g_h2l[0][gi] = z; g_h2l[1][gi] = z;
        g_h2f[0][gi] = 0.f; g_h2f[1][gi] = 0.f;
    }
    grid_barrier();

    float c1 = 0.f, c2 = 0.f;
    const int eb = tid >> 2, ejj = tid & 3;   // epilogue cell (b, jj), tid<256

    for (int t = 0; t < TSTEPS; ++t) {
        int cur = (t + 1) & 1, prv = t & 1;

        // ======== phase A ========
        float acc[2][4] = {{0.f,0.f,0.f,0.f},{0.f,0.f,0.f,0.f}};
        run_phase(su, gbase, 0, t, g, kh, tg, lane, acc);
        store_d(sDf, acc, g, kh, lane);
        __syncthreads();
        if (tid < 256) {
            float4 s0 = *(float4*)(sDf + (0 * 64 + eb) * 16 + ejj * 4);
            float4 s1 = *(float4*)(sDf + (1 * 64 + eb) * 16 + ejj * 4);
            float4 s2 = *(float4*)(sDf + (2 * 64 + eb) * 16 + ejj * 4);
            float4 s3 = *(float4*)(sDf + (3 * 64 + eb) * 16 + ejj * 4);
            float4 bi = *(float4*)(sBIA + ejj * 4);
            float gi = s0.x + s1.x + s2.x + s3.x + bi.x;
            float gf = s0.y + s1.y + s2.y + s3.y + bi.y;
            float gg = s0.z + s1.z + s2.z + s3.z + bi.z;
            float go = s0.w + s1.w + s2.w + s3.w + bi.w;
            float cc = sigf(gf) * c1 + sigf(gi) * tanhf(gg);
            c1 = cc;
            float h = sigf(go) * tanhf(cc);
            bf16 hb = __float2bfloat16(h);
            g_h1h[cur][eb * HD + j0 + ejj] = hb;
            g_h1l[cur][eb * HD + j0 + ejj] = __float2bfloat16(h - __bfloat162float(hb));
        }
        grid_barrier();                         // publish h1(t)

        if (t > 0) do_y(t - 1, g_h2f[prv], c, tid, sWO, sBO, sRY, out);

        // ======== phase B ========
        acc[0][0] = acc[0][1] = acc[0][2] = acc[0][3] = 0.f;
        acc[1][0] = acc[1][1] = acc[1][2] = acc[1][3] = 0.f;
        run_phase(su, gbase, 1, t, g, kh, tg, lane, acc);
        store_d(sDf, acc, g, kh, lane);
        __syncthreads();
        if (tid < 256) {
            float4 s0 = *(float4*)(sDf + (0 * 64 + eb) * 16 + ejj * 4);
            float4 s1 = *(float4*)(sDf + (1 * 64 + eb) * 16 + ejj * 4);
            float4 s2 = *(float4*)(sDf + (2 * 64 + eb) * 16 + ejj * 4);
            float4 s3 = *(float4*)(sDf + (3 * 64 + eb) * 16 + ejj * 4);
            float4 bi = *(float4*)(sBIB + ejj * 4);
            float gi = s0.x + s1.x + s2.x + s3.x + bi.x;
            float gf = s0.y + s1.y + s2.y + s3.y + bi.y;
            float gg = s0.z + s1.z + s2.z + s3.z + bi.z;
            float go = s0.w + s1.w + s2.w + s3.w + bi.w;
            float cc = sigf(gf) * c2 + sigf(gi) * tanhf(gg);
            c2 = cc;
            float h = sigf(go) * tanhf(cc);
            bf16 hb = __float2bfloat16(h);
            g_h2h[cur][eb * HD + j0 + ejj] = hb;
            g_h2l[cur][eb * HD + j0 + ejj] = __float2bfloat16(h - __bfloat162float(hb));
            g_h2f[cur][(j0 + ejj) * 64 + eb] = h;
        }
        __syncthreads();   // protect sDf before next step's stores
    }

    grid_barrier();
    do_y(TSTEPS - 1, g_h2f[0], c, tid, sWO, sBO, sRY, out);
}

extern "C" void kernel_launch(void* const* d_in, const int* in_sizes, int n_in,
                              void* d_out, int out_size) {
    const float* x    = (const float*)d_in[0];
    const float* Wih1 = (const float*)d_in[1];
    const float* Whh1 = (const float*)d_in[2];
    const float* bih1 = (const float*)d_in[3];
    const float* bhh1 = (const float*)d_in[4];
    const float* Wih2 = (const float*)d_in[5];
    const float* Whh2 = (const float*)d_in[6];
    const float* bih2 = (const float*)d_in[7];
    const float* bhh2 = (const float*)d_in[8];
    const float* Wout = (const float*)d_in[9];
    const float* bout = (const float*)d_in[10];
    float* out = (float*)d_out;

    cudaFuncSetAttribute(lstm_mma_kernel,
                         cudaFuncAttributeMaxDynamicSharedMemorySize, SMEM_BYTES);
    lstm_mma_kernel<<<NCTA, NTHR, SMEM_BYTES>>>(
        x, Wih1, Whh1, bih1, bhh1, Wih2, Whh2, bih2, bhh2, Wout, bout, out);
}

// round 16
// speedup vs baseline: 2.4748x; 1.0492x over previous
#include <cuda_runtime.h>
#include <cuda_bf16.h>
#include <math.h>
#include <stdint.h>

#define BATCH 64
#define TSTEPS 1024
#define IND 64
#define HD 512
#define OUTD 64
#define NCTA 128
#define NTHR 512

typedef __nv_bfloat16 bf16;

// ---- SMEM layout (bytes) ----
#define O_BH1 0          // 16 n x 576 k bf16, row stride 1152, XOR swizzle
#define O_BL1 18432
#define O_BH2 36864      // 16 n x 1024 k, row stride 2048
#define O_BL2 69632
#define O_AB  102400     // 4 groups x 4 slots x 4KB (2KB hi + 2KB lo)
#define O_D1  167936     // 4 kh x 64 b x 16 n f32 = 16384
#define O_D2  184320     // 16384
#define O_WO  200704     // 512 f
#define O_RY  202752     // 512 f
#define O_BIA 204800     // 16 f
#define O_BIB 204864     // 16 f
#define O_BO  204928
#define SMEM_BYTES 204936

__device__ __align__(16) bf16 g_xh[TSTEPS * BATCH * IND];
__device__ __align__(16) bf16 g_xl[TSTEPS * BATCH * IND];
__device__ __align__(16) bf16 g_h1h[2][BATCH * HD];   // [b][j]
__device__ __align__(16) bf16 g_h1l[2][BATCH * HD];
__device__ __align__(16) bf16 g_h2h[2][BATCH * HD];
__device__ __align__(16) bf16 g_h2l[2][BATCH * HD];
__device__ __align__(16) float g_h2f[2][HD * BATCH];  // [j][b] for y head
__device__ unsigned g_gen, g_count;

__device__ __forceinline__ void grid_barrier() {
    __syncthreads();
    if (threadIdx.x == 0) {
        __threadfence();
        volatile unsigned* vg = &g_gen;
        unsigned my = *vg;
        if (atomicAdd(&g_count, 1u) == NCTA - 1u) {
            g_count = 0u; __threadfence(); *vg = my + 1u;
        } else { while (*vg == my) { } }
        __threadfence();
    }
    __syncthreads();
}

__device__ __forceinline__ float sigf(float x) { return 1.0f / (1.0f + __expf(-x)); }
__device__ __forceinline__ uint32_t smem_u32(const void* p) {
    uint32_t a;
    asm("{ .reg .u64 t; cvta.to.shared.u64 t, %1; cvt.u32.u64 %0, t; }" : "=r"(a) : "l"(p));
    return a;
}
#define CPA16(dst, src) \
    asm volatile("cp.async.cg.shared.global [%0], [%1], 16;" :: "r"(dst), "l"(src) : "memory")

__device__ __forceinline__ void ldsm4(uint32_t (&r)[4], uint32_t addr) {
    asm volatile("ldmatrix.sync.aligned.m8n8.x4.shared.b16 {%0,%1,%2,%3}, [%4];"
        : "=r"(r[0]), "=r"(r[1]), "=r"(r[2]), "=r"(r[3]) : "r"(addr));
}
__device__ __forceinline__ void mma_bf(float (&d)[4], const uint32_t (&a)[4],
                                       uint32_t b0, uint32_t b1) {
    asm volatile("mma.sync.aligned.m16n8k16.row.col.f32.bf16.bf16.f32 "
        "{%0,%1,%2,%3}, {%4,%5,%6,%7}, {%8,%9}, {%0,%1,%2,%3};"
        : "+f"(d[0]), "+f"(d[1]), "+f"(d[2]), "+f"(d[3])
        : "r"(a[0]), "r"(a[1]), "r"(a[2]), "r"(a[3]), "r"(b0), "r"(b1));
}

// ---- fused-step chunk sources ----
// i==0: x(t); i in 1..8: h1(t-1) [buf (t+1)&1]; i in 9..16: h2(t-2) [buf t&1]
__device__ __forceinline__ void asrc_f(int t, int i,
                                       const bf16*& ph, const bf16*& pl, int& st) {
    if (i == 0) { ph = g_xh + t * 4096; pl = g_xl + t * 4096; st = IND; }
    else if (i <= 8) {
        int o = (i - 1) * 64, p = (t + 1) & 1;
        ph = g_h1h[p] + o; pl = g_h1l[p] + o; st = HD;
    } else {
        int o = (i - 9) * 64, p = t & 1;
        ph = g_h2h[p] + o; pl = g_h2l[p] + o; st = HD;
    }
}
// group g loads ITS 16 rows of chunk i (2KB hi + 2KB lo), XOR swizzle, commit
__device__ __forceinline__ void achunk(int t, int i, uint32_t gbase, int g, int tg) {
    const bf16 *ph, *pl; int st;
    asrc_f(t, i, ph, pl, st);
    int lrow = tg >> 3, seg = tg & 7;
    uint32_t d = (uint32_t)(lrow * 128 + ((seg ^ (lrow & 7)) << 4));
    uint32_t db = gbase + (uint32_t)(i & 3) * 4096u + d;
    CPA16(db, ph + (g * 16 + lrow) * st + seg * 8);
    CPA16(db + 2048u, pl + (g * 16 + lrow) * st + seg * 8);
    asm volatile("cp.async.commit_group;" ::: "memory");
}

// fused pipeline: acc1 <- [x | h1(t-1)] * B1 ; acc2 <- [h1(t-1) | h2(t-2)] * B2
__device__ void run_fused(uint32_t su, uint32_t gbase, int t, int doL1, int doL2,
                          int g, int kh, int tg, int lane,
                          float (&a1)[2][4], float (&a2)[2][4]) {
    const int i0 = doL1 ? 0 : 1;
    const int i1 = doL2 ? 16 : 8;
    achunk(t, i0, gbase, g, tg);
    achunk(t, i0 + 1, gbase, g, tg);
    achunk(t, i0 + 2, gbase, g, tg);
    int lrow = lane & 15;
    uint32_t ksg = (uint32_t)(kh * 2 + (lane >> 4));
    uint32_t aoff = (uint32_t)(lrow * 128) + ((ksg ^ (uint32_t)(lrow & 7)) << 4);
    int n = ((lane >> 4) << 3) + (lane & 7);
    int ks2 = (lane >> 3) & 1;
    for (int i = i0; i <= i1; ++i) {
        int rem = i1 - i;
        if (rem >= 2)      asm volatile("cp.async.wait_group 2;" ::: "memory");
        else if (rem == 1) asm volatile("cp.async.wait_group 1;" ::: "memory");
        else               asm volatile("cp.async.wait_group 0;" ::: "memory");
        asm volatile("bar.sync %0, 128;" :: "r"(1 + g) : "memory");
        uint32_t abase = gbase + (uint32_t)(i & 3) * 4096u;
        uint32_t ah[4], al[4], bh[4], bl[4];
        ldsm4(ah, abase + aoff);
        ldsm4(al, abase + 2048u + aoff);
        if (doL1 && i <= 8) {            // B1 k-tile 4i+kh
            int kg = 4 * i + kh;
            uint32_t kb2 = (uint32_t)(kg * 32 + (ks2 << 4));
            uint32_t boff = (uint32_t)n * 1152u + (kb2 & ~127u) +
                            ((kb2 & 127u) ^ (uint32_t)((n & 7) << 4));
            ldsm4(bh, su + O_BH1 + boff);
            ldsm4(bl, su + O_BL1 + boff);
            mma_bf(a1[0], ah, bh[0], bh[1]); mma_bf(a1[1], ah, bh[2], bh[3]);
            mma_bf(a1[0], al, bh[0], bh[1]); mma_bf(a1[1], al, bh[2], bh[3]);
            mma_bf(a1[0], ah, bl[0], bl[1]); mma_bf(a1[1], ah, bl[2], bl[3]);
        }
        if (doL2 && i >= 1) {            // B2 k-tile 4(i-1)+kh
            int kg = 4 * (i - 1) + kh;
            uint32_t kb2 = (uint32_t)(kg * 32 + (ks2 << 4));
            uint32_t boff = (uint32_t)n * 2048u + (kb2 & ~127u) +
                            ((kb2 & 127u) ^ (uint32_t)((n & 7) << 4));
            ldsm4(bh, su + O_BH2 + boff);
            ldsm4(bl, su + O_BL2 + boff);
            mma_bf(a2[0], ah, bh[0], bh[1]); mma_bf(a2[1], ah, bh[2], bh[3]);
            mma_bf(a2[0], al, bh[0], bh[1]); mma_bf(a2[1], al, bh[2], bh[3]);
            mma_bf(a2[0], ah, bl[0], bl[1]); mma_bf(a2[1], ah, bl[2], bl[3]);
        }
        if (i + 3 <= i1) achunk(t, i + 3, gbase, g, tg);
    }
}

__device__ __forceinline__ void store_d(float* sDf, const float (&acc)[2][4],
                                        int g, int kh, int lane) {
    int base = ((kh * 64) + g * 16 + (lane >> 2)) * 16 + (lane & 3) * 2;
    *(float2*)(sDf + base)           = make_float2(acc[0][0], acc[0][1]);
    *(float2*)(sDf + base + 128)     = make_float2(acc[0][2], acc[0][3]);
    *(float2*)(sDf + base + 8)       = make_float2(acc[1][0], acc[1][1]);
    *(float2*)(sDf + base + 128 + 8) = make_float2(acc[1][2], acc[1][3]);
}

__device__ __forceinline__ float4 gather_d(const float* sDf, int eb, int ejj) {
    float4 s0 = *(const float4*)(sDf + (0 * 64 + eb) * 16 + ejj * 4);
    float4 s1 = *(const float4*)(sDf + (1 * 64 + eb) * 16 + ejj * 4);
    float4 s2 = *(const float4*)(sDf + (2 * 64 + eb) * 16 + ejj * 4);
    float4 s3 = *(const float4*)(sDf + (3 * 64 + eb) * 16 + ejj * 4);
    return make_float4(s0.x + s1.x + s2.x + s3.x, s0.y + s1.y + s2.y + s3.y,
                       s0.z + s1.z + s2.z + s3.z, s0.w + s1.w + s2.w + s3.w);
}

__device__ __forceinline__ void do_y(int t, const float* __restrict__ h2v,
                                     int cta, int tid, const float* sWO,
                                     const float* sBO, float* sRY, float* __restrict__ out) {
    int b = tid & 63, u = tid >> 6;
    if (cta < OUTD) {
        float p = 0.0f; int k0 = u * 64;
#pragma unroll 8
        for (int k = 0; k < 64; ++k)
            p += __ldcg(h2v + (k0 + k) * 64 + b) * sWO[k0 + k];
        sRY[u * 64 + b] = p;
    }
    __syncthreads();
    if (cta < OUTD && u == 0) {
        float y = sBO[0];
#pragma unroll
        for (int m = 0; m < 8; ++m) y += sRY[m * 64 + b];
        out[b * (TSTEPS * OUTD) + t * OUTD + cta] = y;
    }
}

extern __shared__ char smem[];

__global__ void __launch_bounds__(NTHR, 1)
lstm_mma_kernel(const float* __restrict__ x,
                const float* __restrict__ Wih1, const float* __restrict__ Whh1,
                const float* __restrict__ bih1, const float* __restrict__ bhh1,
                const float* __restrict__ Wih2, const float* __restrict__ Whh2,
                const float* __restrict__ bih2, const float* __restrict__ bhh2,
                const float* __restrict__ Wout, const float* __restrict__ bout,
                float* __restrict__ out) {
    const int tid = threadIdx.x, c = blockIdx.x, j0 = c * 4;
    const int lane = tid & 31;
    const int g = tid >> 7;            // mt group 0..3 (warps contiguous)
    const int kh = (tid >> 5) & 3;     // k slice 0..3
    const int tg = tid & 127;          // thread-in-group
    uint32_t su = smem_u32(smem);
    uint32_t gbase = su + O_AB + (uint32_t)g * 16384u;
    float* sWO = (float*)(smem + O_WO);
    float* sBO = (float*)(smem + O_BO);
    float* sRY = (float*)(smem + O_RY);
    float* sBIA = (float*)(smem + O_BIA);
    float* sBIB = (float*)(smem + O_BIB);
    float* sD1 = (float*)(smem + O_D1);
    float* sD2 = (float*)(smem + O_D2);

    // ---- stage split weights: B row n = jj*4+tp -> weight row tp*HD+j0+jj ----
    for (int i = tid; i < 16 * 576; i += NTHR) {
        int n = i / 576, k = i - n * 576;
        int row = (n & 3) * HD + j0 + (n >> 2);
        float v = (k < IND) ? Wih1[row * IND + k] : Whh1[row * HD + (k - IND)];
        bf16 h = __float2bfloat16(v);
        bf16 l = __float2bfloat16(v - __bfloat162float(h));
        uint32_t k2 = (uint32_t)(k * 2);
        uint32_t off = (uint32_t)n * 1152u + (k2 & ~127u) + ((k2 & 127u) ^ (uint32_t)((n & 7) << 4));
        *(bf16*)(smem + O_BH1 + off) = h;
        *(bf16*)(smem + O_BL1 + off) = l;
    }
    for (int i = tid; i < 16 * 1024; i += NTHR) {
        int n = i >> 10, k = i & 1023;
        int row = (n & 3) * HD + j0 + (n >> 2);
        float v = (k < HD) ? Wih2[row * HD + k] : Whh2[row * HD + (k - HD)];
        bf16 h = __float2bfloat16(v);
        bf16 l = __float2bfloat16(v - __bfloat162float(h));
        uint32_t k2 = (uint32_t)(k * 2);
        uint32_t off = (uint32_t)n * 2048u + (k2 & ~127u) + ((k2 & 127u) ^ (uint32_t)((n & 7) << 4));
        *(bf16*)(smem + O_BH2 + off) = h;
        *(bf16*)(smem + O_BL2 + off) = l;
    }
    if (tid < 16) {
        int row = (tid & 3) * HD + j0 + (tid >> 2);
        sBIA[tid] = bih1[row] + bhh1[row];
        sBIB[tid] = bih2[row] + bhh2[row];
    }
    if (c < OUTD) {
        for (int i = tid; i < HD; i += NTHR) sWO[i] = Wout[c * HD + i];
        if (tid == 0) sBO[0] = bout[c];
    }

    // ---- x -> bf16 split [t][b][k]; zero h state ----
    for (int t = c * (TSTEPS / NCTA); t < (c + 1) * (TSTEPS / NCTA); ++t)
        for (int i = tid; i < BATCH * IND; i += NTHR) {
            int b = i >> 6, k = i & 63;
            float v = x[b * (TSTEPS * IND) + t * IND + k];
            bf16 h = __float2bfloat16(v);
            g_xh[t * 4096 + i] = h;
            g_xl[t * 4096 + i] = __float2bfloat16(v - __bfloat162float(h));
        }
    if (c < 64) {
        int gi = c * NTHR + tid;   // 32768 = BATCH*HD
        bf16 z = __float2bfloat16(0.f);
        g_h1h[0][gi] = z; g_h1h[1][gi] = z;
        g_h1l[0][gi] = z; g_h1l[1][gi] = z;
        g_h2h[0][gi] = z; g_h2h[1][gi] = z;
        g_h2l[0][gi] = z; g_h2l[1][gi] = z;
        g_h2f[0][gi] = 0.f; g_h2f[1][gi] = 0.f;
    }
    grid_barrier();

    float c1 = 0.f, c2 = 0.f;
    const int eb = tid >> 2, ejj = tid & 3;   // epilogue cell (b, jj), tid<256

    // fused skewed loop: iteration t computes gates1(t) [t<T] and gates2(t-1) [t>0]
    for (int t = 0; t <= TSTEPS; ++t) {
        const int doL1 = (t < TSTEPS), doL2 = (t > 0);
        float a1[2][4] = {{0.f,0.f,0.f,0.f},{0.f,0.f,0.f,0.f}};
        float a2[2][4] = {{0.f,0.f,0.f,0.f},{0.f,0.f,0.f,0.f}};
        run_fused(su, gbase, t, doL1, doL2, g, kh, tg, lane, a1, a2);
        if (doL1) store_d(sD1, a1, g, kh, lane);
        if (doL2) store_d(sD2, a2, g, kh, lane);
        __syncthreads();
        if (tid < 256) {
            if (doL1) {       // layer1 cell update for step t -> h1 buf[t&1]
                float4 gsum = gather_d(sD1, eb, ejj);
                float4 bi = *(float4*)(sBIA + ejj * 4);
                float cc = sigf(gsum.y + bi.y) * c1 +
                           sigf(gsum.x + bi.x) * tanhf(gsum.z + bi.z);
                c1 = cc;
                float h = sigf(gsum.w + bi.w) * tanhf(cc);
                bf16 hb = __float2bfloat16(h);
                g_h1h[t & 1][eb * HD + j0 + ejj] = hb;
                g_h1l[t & 1][eb * HD + j0 + ejj] = __float2bfloat16(h - __bfloat162float(hb));
            }
            if (doL2) {       // layer2 cell update for step t-1 -> h2 buf[(t+1)&1]
                float4 gsum = gather_d(sD2, eb, ejj);
                float4 bi = *(float4*)(sBIB + ejj * 4);
                float cc = sigf(gsum.y + bi.y) * c2 +
                           sigf(gsum.x + bi.x) * tanhf(gsum.z + bi.z);
                c2 = cc;
                float h = sigf(gsum.w + bi.w) * tanhf(cc);
                bf16 hb = __float2bfloat16(h);
                int p = (t + 1) & 1;
                g_h2h[p][eb * HD + j0 + ejj] = hb;
                g_h2l[p][eb * HD + j0 + ejj] = __float2bfloat16(h - __bfloat162float(hb));
                g_h2f[p][(j0 + ejj) * 64 + eb] = h;
            }
        }
        grid_barrier();       // publish h1(t), h2(t-1); the ONLY barrier per step
        if (t >= 1) do_y(t - 1, g_h2f[(t + 1) & 1], c, tid, sWO, sBO, sRY, out);
    }
}

extern "C" void kernel_launch(void* const* d_in, const int* in_sizes, int n_in,
                              void* d_out, int out_size) {
    const float* x    = (const float*)d_in[0];
    const float* Wih1 = (const float*)d_in[1];
    const float* Whh1 = (const float*)d_in[2];
    const float* bih1 = (const float*)d_in[3];
    const float* bhh1 = (const float*)d_in[4];
    const float* Wih2 = (const float*)d_in[5];
    const float* Whh2 = (const float*)d_in[6];
    const float* bih2 = (const float*)d_in[7];
    const float* bhh2 = (const float*)d_in[8];
    const float* Wout = (const float*)d_in[9];
    const float* bout = (const float*)d_in[10];
    float* out = (float*)d_out;

    cudaFuncSetAttribute(lstm_mma_kernel,
                         cudaFuncAttributeMaxDynamicSharedMemorySize, SMEM_BYTES);
    lstm_mma_kernel<<<NCTA, NTHR, SMEM_BYTES>>>(
        x, Wih1, Whh1, bih1, bhh1, Wih2, Whh2, bih2, bhh2, Wout, bout, out);
}

// round 17
// speedup vs baseline: 2.7735x; 1.1207x over previous
#include <cuda_runtime.h>
#include <cuda_fp16.h>
#include <math.h>
#include <stdint.h>

#define BATCH 64
#define TSTEPS 1024
#define IND 64
#define HD 512
#define OUTD 64
#define NCTA 128
#define NTHR 512

typedef __half hf;

// ---- SMEM layout (bytes) ----
#define O_BH1 0          // 16 n x 576 k fp16, row stride 1152, XOR swizzle
#define O_BL1 18432
#define O_BH2 36864      // 16 n x 1024 k, row stride 2048
#define O_BL2 69632
#define O_AB  102400     // 4 groups x 4 slots x 2KB
#define O_D1  135168     // 4 kh x 64 b x 16 n f32 = 16384
#define O_D2  151552
#define O_WO  167936     // 512 f
#define O_RY  169984     // 512 f
#define O_BIA 172032     // 16 f
#define O_BIB 172096     // 16 f
#define O_BO  172160
#define SMEM_BYTES 172176

__device__ __align__(16) hf g_xh[TSTEPS * BATCH * IND];
__device__ __align__(16) hf g_h1[2][BATCH * HD];      // [b][j] fp16
__device__ __align__(16) hf g_h2[2][BATCH * HD];
__device__ __align__(16) float g_h2f[2][HD * BATCH];  // [j][b] for y head
__device__ unsigned g_gen, g_count;

__device__ __forceinline__ void grid_barrier() {
    __syncthreads();
    if (threadIdx.x == 0) {
        __threadfence();
        volatile unsigned* vg = &g_gen;
        unsigned my = *vg;
        if (atomicAdd(&g_count, 1u) == NCTA - 1u) {
            g_count = 0u; __threadfence(); *vg = my + 1u;
        } else { while (*vg == my) { } }
        __threadfence();
    }
    __syncthreads();
}

__device__ __forceinline__ float sigf(float x) { return 1.0f / (1.0f + __expf(-x)); }
__device__ __forceinline__ uint32_t smem_u32(const void* p) {
    uint32_t a;
    asm("{ .reg .u64 t; cvta.to.shared.u64 t, %1; cvt.u32.u64 %0, t; }" : "=r"(a) : "l"(p));
    return a;
}
#define CPA16(dst, src) \
    asm volatile("cp.async.cg.shared.global [%0], [%1], 16;" :: "r"(dst), "l"(src) : "memory")

__device__ __forceinline__ void ldsm4(uint32_t (&r)[4], uint32_t addr) {
    asm volatile("ldmatrix.sync.aligned.m8n8.x4.shared.b16 {%0,%1,%2,%3}, [%4];"
        : "=r"(r[0]), "=r"(r[1]), "=r"(r[2]), "=r"(r[3]) : "r"(addr));
}
__device__ __forceinline__ void mma_hf(float (&d)[4], const uint32_t (&a)[4],
                                       uint32_t b0, uint32_t b1) {
    asm volatile("mma.sync.aligned.m16n8k16.row.col.f32.f16.f16.f32 "
        "{%0,%1,%2,%3}, {%4,%5,%6,%7}, {%8,%9}, {%0,%1,%2,%3};"
        : "+f"(d[0]), "+f"(d[1]), "+f"(d[2]), "+f"(d[3])
        : "r"(a[0]), "r"(a[1]), "r"(a[2]), "r"(a[3]), "r"(b0), "r"(b1));
}

// ---- fused-step chunk sources (single fp16 stream) ----
// i==0: x(t); i in 1..8: h1(t-1) [buf (t+1)&1]; i in 9..16: h2(t-2) [buf t&1]
__device__ __forceinline__ void asrc_f(int t, int i, const hf*& ph, int& st) {
    if (i == 0) { ph = g_xh + t * 4096; st = IND; }
    else if (i <= 8) { ph = g_h1[(t + 1) & 1] + (i - 1) * 64; st = HD; }
    else { ph = g_h2[t & 1] + (i - 9) * 64; st = HD; }
}
// group g loads ITS 16 rows of chunk i (2KB), XOR swizzle, commit
__device__ __forceinline__ void achunk(int t, int i, uint32_t gbase, int g, int tg) {
    const hf* ph; int st;
    asrc_f(t, i, ph, st);
    int lrow = tg >> 3, seg = tg & 7;
    uint32_t d = (uint32_t)(lrow * 128 + ((seg ^ (lrow & 7)) << 4));
    CPA16(gbase + (uint32_t)(i & 3) * 2048u + d, ph + (g * 16 + lrow) * st + seg * 8);
    asm volatile("cp.async.commit_group;" ::: "memory");
}

// one pipeline iteration (W must be a literal)
#define ITER(i, D1, D2, W, LD) do {                                           \
    asm volatile("cp.async.wait_group " #W ";" ::: "memory");                 \
    asm volatile("bar.sync %0, 128;" :: "r"(1 + g) : "memory");               \
    uint32_t ah[4];                                                           \
    ldsm4(ah, gbase + (uint32_t)(((i) & 3) * 2048) + aoff);                   \
    if (D1) {                                                                 \
        uint32_t bh[4], bl[4];                                                \
        uint32_t bo = b1base + (uint32_t)(128 * (i));                         \
        ldsm4(bh, bo); ldsm4(bl, bo + 18432u);                                \
        mma_hf(a1[0], ah, bh[0], bh[1]); mma_hf(a1[1], ah, bh[2], bh[3]);     \
        mma_hf(a1[0], ah, bl[0], bl[1]); mma_hf(a1[1], ah, bl[2], bl[3]);     \
    }                                                                         \
    if (D2) {                                                                 \
        uint32_t bh[4], bl[4];                                                \
        uint32_t bo = b2base + (uint32_t)(128 * ((i) - 1));                   \
        ldsm4(bh, bo); ldsm4(bl, bo + 32768u);                                \
        mma_hf(a2[0], ah, bh[0], bh[1]); mma_hf(a2[1], ah, bh[2], bh[3]);     \
        mma_hf(a2[0], ah, bl[0], bl[1]); mma_hf(a2[1], ah, bl[2], bl[3]);     \
    }                                                                         \
    if (LD) achunk(t, (i) + 3, gbase, g, tg);                                 \
} while (0)

// common case t in [1, T-1]: fully unrolled, both layers
__device__ __forceinline__ void run_both(uint32_t gbase, int t, int g, int tg,
                                         uint32_t aoff, uint32_t b1base, uint32_t b2base,
                                         float (&a1)[2][4], float (&a2)[2][4]) {
    achunk(t, 0, gbase, g, tg);
    achunk(t, 1, gbase, g, tg);
    achunk(t, 2, gbase, g, tg);
    ITER(0, 1, 0, 2, 1);
#pragma unroll
    for (int i = 1; i <= 8; ++i) ITER(i, 1, 1, 2, 1);
#pragma unroll
    for (int i = 9; i <= 13; ++i) ITER(i, 0, 1, 2, 1);
    ITER(14, 0, 1, 2, 0);
    ITER(15, 0, 1, 1, 0);
    ITER(16, 0, 1, 0, 0);
}

// edge steps (t==0: L1 only; t==T: L2 only) — compact dynamic loop
__device__ void run_edge(uint32_t gbase, int t, int doL1, int g, int tg,
                         uint32_t aoff, uint32_t b1base, uint32_t b2base,
                         float (&a1)[2][4], float (&a2)[2][4]) {
    const int i0 = doL1 ? 0 : 1;
    const int i1 = doL1 ? 8 : 16;
    achunk(t, i0, gbase, g, tg);
    achunk(t, i0 + 1, gbase, g, tg);
    achunk(t, i0 + 2, gbase, g, tg);
    for (int i = i0; i <= i1; ++i) {
        int rem = i1 - i;
        if (rem >= 2)      asm volatile("cp.async.wait_group 2;" ::: "memory");
        else if (rem == 1) asm volatile("cp.async.wait_group 1;" ::: "memory");
        else               asm volatile("cp.async.wait_group 0;" ::: "memory");
        asm volatile("bar.sync %0, 128;" :: "r"(1 + g) : "memory");
        uint32_t ah[4];
        ldsm4(ah, gbase + (uint32_t)((i & 3) * 2048) + aoff);
        if (doL1) {
            uint32_t bh[4], bl[4];
            uint32_t bo = b1base + (uint32_t)(128 * i);
            ldsm4(bh, bo); ldsm4(bl, bo + 18432u);
            mma_hf(a1[0], ah, bh[0], bh[1]); mma_hf(a1[1], ah, bh[2], bh[3]);
            mma_hf(a1[0], ah, bl[0], bl[1]); mma_hf(a1[1], ah, bl[2], bl[3]);
        } else {
            uint32_t bh[4], bl[4];
            uint32_t bo = b2base + (uint32_t)(128 * (i - 1));
            ldsm4(bh, bo); ldsm4(bl, bo + 32768u);
            mma_hf(a2[0], ah, bh[0], bh[1]); mma_hf(a2[1], ah, bh[2], bh[3]);
            mma_hf(a2[0], ah, bl[0], bl[1]); mma_hf(a2[1], ah, bl[2], bl[3]);
        }
        if (i + 3 <= i1) achunk(t, i + 3, gbase, g, tg);
    }
}

__device__ __forceinline__ void store_d(float* sDf, const float (&acc)[2][4],
                                        int g, int kh, int lane) {
    int base = ((kh * 64) + g * 16 + (lane >> 2)) * 16 + (lane & 3) * 2;
    *(float2*)(sDf + base)           = make_float2(acc[0][0], acc[0][1]);
    *(float2*)(sDf + base + 128)     = make_float2(acc[0][2], acc[0][3]);
    *(float2*)(sDf + base + 8)       = make_float2(acc[1][0], acc[1][1]);
    *(float2*)(sDf + base + 128 + 8) = make_float2(acc[1][2], acc[1][3]);
}

__device__ __forceinline__ float4 gather_d(const float* sDf, int eb, int ejj) {
    float4 s0 = *(const float4*)(sDf + (0 * 64 + eb) * 16 + ejj * 4);
    float4 s1 = *(const float4*)(sDf + (1 * 64 + eb) * 16 + ejj * 4);
    float4 s2 = *(const float4*)(sDf + (2 * 64 + eb) * 16 + ejj * 4);
    float4 s3 = *(const float4*)(sDf + (3 * 64 + eb) * 16 + ejj * 4);
    return make_float4(s0.x + s1.x + s2.x + s3.x, s0.y + s1.y + s2.y + s3.y,
                       s0.z + s1.z + s2.z + s3.z, s0.w + s1.w + s2.w + s3.w);
}

__device__ __forceinline__ void do_y(int t, const float* __restrict__ h2v,
                                     int cta, int tid, const float* sWO,
                                     const float* sBO, float* sRY, float* __restrict__ out) {
    int b = tid & 63, u = tid >> 6;
    if (cta < OUTD) {
        float p = 0.0f; int k0 = u * 64;
#pragma unroll 8
        for (int k = 0; k < 64; ++k)
            p += __ldcg(h2v + (k0 + k) * 64 + b) * sWO[k0 + k];
        sRY[u * 64 + b] = p;
    }
    __syncthreads();
    if (cta < OUTD && u == 0) {
        float y = sBO[0];
#pragma unroll
        for (int m = 0; m < 8; ++m) y += sRY[m * 64 + b];
        out[b * (TSTEPS * OUTD) + t * OUTD + cta] = y;
    }
}

extern __shared__ char smem[];

__global__ void __launch_bounds__(NTHR, 1)
lstm_mma_kernel(const float* __restrict__ x,
                const float* __restrict__ Wih1, const float* __restrict__ Whh1,
                const float* __restrict__ bih1, const float* __restrict__ bhh1,
                const float* __restrict__ Wih2, const float* __restrict__ Whh2,
                const float* __restrict__ bih2, const float* __restrict__ bhh2,
                const float* __restrict__ Wout, const float* __restrict__ bout,
                float* __restrict__ out) {
    const int tid = threadIdx.x, c = blockIdx.x, j0 = c * 4;
    const int lane = tid & 31;
    const int g = tid >> 7;            // mt group 0..3 (warps contiguous)
    const int kh = (tid >> 5) & 3;     // k slice 0..3
    const int tg = tid & 127;          // thread-in-group
    uint32_t su = smem_u32(smem);
    uint32_t gbase = su + O_AB + (uint32_t)g * 8192u;
    float* sWO = (float*)(smem + O_WO);
    float* sBO = (float*)(smem + O_BO);
    float* sRY = (float*)(smem + O_RY);
    float* sBIA = (float*)(smem + O_BIA);
    float* sBIB = (float*)(smem + O_BIB);
    float* sD1 = (float*)(smem + O_D1);
    float* sD2 = (float*)(smem + O_D2);

    // ---- stage split fp16 weights: B row n = jj*4+tp -> weight row tp*HD+j0+jj ----
    for (int i = tid; i < 16 * 576; i += NTHR) {
        int n = i / 576, k = i - n * 576;
        int row = (n & 3) * HD + j0 + (n >> 2);
        float v = (k < IND) ? Wih1[row * IND + k] : Whh1[row * HD + (k - IND)];
        hf h = __float2half_rn(v);
        hf l = __float2half_rn(v - __half2float(h));
        uint32_t k2 = (uint32_t)(k * 2);
        uint32_t off = (uint32_t)n * 1152u + (k2 & ~127u) + ((k2 & 127u) ^ (uint32_t)((n & 7) << 4));
        *(hf*)(smem + O_BH1 + off) = h;
        *(hf*)(smem + O_BL1 + off) = l;
    }
    for (int i = tid; i < 16 * 1024; i += NTHR) {
        int n = i >> 10, k = i & 1023;
        int row = (n & 3) * HD + j0 + (n >> 2);
        float v = (k < HD) ? Wih2[row * HD + k] : Whh2[row * HD + (k - HD)];
        hf h = __float2half_rn(v);
        hf l = __float2half_rn(v - __half2float(h));
        uint32_t k2 = (uint32_t)(k * 2);
        uint32_t off = (uint32_t)n * 2048u + (k2 & ~127u) + ((k2 & 127u) ^ (uint32_t)((n & 7) << 4));
        *(hf*)(smem + O_BH2 + off) = h;
        *(hf*)(smem + O_BL2 + off) = l;
    }
    if (tid < 16) {
        int row = (tid & 3) * HD + j0 + (tid >> 2);
        sBIA[tid] = bih1[row] + bhh1[row];
        sBIB[tid] = bih2[row] + bhh2[row];
    }
    if (c < OUTD) {
        for (int i = tid; i < HD; i += NTHR) sWO[i] = Wout[c * HD + i];
        if (tid == 0) sBO[0] = bout[c];
    }

    // ---- x -> fp16 [t][b][k]; zero h state ----
    for (int t = c * (TSTEPS / NCTA); t < (c + 1) * (TSTEPS / NCTA); ++t)
        for (int i = tid; i < BATCH * IND; i += NTHR) {
            int b = i >> 6, k = i & 63;
            g_xh[t * 4096 + i] = __float2half_rn(x[b * (TSTEPS * IND) + t * IND + k]);
        }
    if (c < 64) {
        int gi = c * NTHR + tid;   // 32768 = BATCH*HD
        hf z = __float2half_rn(0.f);
        g_h1[0][gi] = z; g_h1[1][gi] = z;
        g_h2[0][gi] = z; g_h2[1][gi] = z;
        g_h2f[0][gi] = 0.f; g_h2f[1][gi] = 0.f;
    }
    grid_barrier();

    // ---- t-invariant fragment addresses ----
    const int lrow = lane & 15;
    const uint32_t ksg = (uint32_t)(kh * 2 + (lane >> 4));
    const uint32_t aoff = (uint32_t)(lrow * 128) + ((ksg ^ (uint32_t)(lrow & 7)) << 4);
    const int n = ((lane >> 4) << 3) + (lane & 7);
    const int ks2 = (lane >> 3) & 1;
    const uint32_t xorp = (uint32_t)((32 * kh + 16 * ks2) ^ ((n & 7) << 4));
    const uint32_t b1base = su + O_BH1 + (uint32_t)n * 1152u + xorp;
    const uint32_t b2base = su + O_BH2 + (uint32_t)n * 2048u + xorp;

    float c1 = 0.f, c2 = 0.f;
    const int eb = tid >> 2, ejj = tid & 3;   // epilogue cell (b, jj), tid<256

    // fused skewed loop: iteration t computes gates1(t) [t<T] and gates2(t-1) [t>0]
    for (int t = 0; t <= TSTEPS; ++t) {
        const int doL1 = (t < TSTEPS), doL2 = (t > 0);
        float a1[2][4] = {{0.f,0.f,0.f,0.f},{0.f,0.f,0.f,0.f}};
        float a2[2][4] = {{0.f,0.f,0.f,0.f},{0.f,0.f,0.f,0.f}};
        if (doL1 && doL2)
            run_both(gbase, t, g, tg, aoff, b1base, b2base, a1, a2);
        else
            run_edge(gbase, t, doL1, g, tg, aoff, b1base, b2base, a1, a2);
        if (doL1) store_d(sD1, a1, g, kh, lane);
        if (doL2) store_d(sD2, a2, g, kh, lane);
        __syncthreads();
        if (tid < 256) {
            if (doL1) {       // layer1 cell update for step t -> h1 buf[t&1]
                float4 gsum = gather_d(sD1, eb, ejj);
                float4 bi = *(float4*)(sBIA + ejj * 4);
                float cc = sigf(gsum.y + bi.y) * c1 +
                           sigf(gsum.x + bi.x) * tanhf(gsum.z + bi.z);
                c1 = cc;
                float h = sigf(gsum.w + bi.w) * tanhf(cc);
                g_h1[t & 1][eb * HD + j0 + ejj] = __float2half_rn(h);
            }
            if (doL2) {       // layer2 cell update for step t-1 -> h2 buf[(t+1)&1]
                float4 gsum = gather_d(sD2, eb, ejj);
                float4 bi = *(float4*)(sBIB + ejj * 4);
                float cc = sigf(gsum.y + bi.y) * c2 +
                           sigf(gsum.x + bi.x) * tanhf(gsum.z + bi.z);
                c2 = cc;
                float h = sigf(gsum.w + bi.w) * tanhf(cc);
                int p = (t + 1) & 1;
                g_h2[p][eb * HD + j0 + ejj] = __float2half_rn(h);
                g_h2f[p][(j0 + ejj) * 64 + eb] = h;
            }
        }
        grid_barrier();       // publish h1(t), h2(t-1); the ONLY barrier per step
        if (t >= 1) do_y(t - 1, g_h2f[(t + 1) & 1], c, tid, sWO, sBO, sRY, out);
    }
}

extern "C" void kernel_launch(void* const* d_in, const int* in_sizes, int n_in,
                              void* d_out, int out_size) {
    const float* x    = (const float*)d_in[0];
    const float* Wih1 = (const float*)d_in[1];
    const float* Whh1 = (const float*)d_in[2];
    const float* bih1 = (const float*)d_in[3];
    const float* bhh1 = (const float*)d_in[4];
    const float* Wih2 = (const float*)d_in[5];
    const float* Whh2 = (const float*)d_in[6];
    const float* bih2 = (const float*)d_in[7];
    const float* bhh2 = (const float*)d_in[8];
    const float* Wout = (const float*)d_in[9];
    const float* bout = (const float*)d_in[10];
    float* out = (float*)d_out;

    cudaFuncSetAttribute(lstm_mma_kernel,
                         cudaFuncAttributeMaxDynamicSharedMemorySize, SMEM_BYTES);
    lstm_mma_kernel<<<NCTA, NTHR, SMEM_BYTES>>>(
        x, Wih1, Whh1, bih1, bhh1, Wih2, Whh2, bih2, bhh2, Wout, bout, out);
}